// round 1
// baseline (speedup 1.0000x reference)
#include <cuda_runtime.h>
#include <math.h>

#define T_LEN 128
#define NB    1024           // BS * A
#define D_IN  128
#define H_DIM 512
#define G_DIM 1536           // 3*H
#define ROWS  (T_LEN * NB)   // 131072

// Scratch (allocation-free rule: __device__ globals)
__device__ float g_x[(size_t)ROWS * H_DIM];    // [t*NB+n][512]
__device__ float g_gi[(size_t)ROWS * G_DIM];   // [t*NB+n][1536]
__device__ float g_h[2][NB * H_DIM];           // ping-pong hidden state

__device__ __forceinline__ float sigf(float x) { return 1.0f / (1.0f + expf(-x)); }

// ---------------------------------------------------------------------------
// init: zero h0, set out = bv
// ---------------------------------------------------------------------------
__global__ void init_kernel(float* __restrict__ out, const float* __restrict__ bv) {
    int i = blockIdx.x * blockDim.x + threadIdx.x;
    if (i < NB * H_DIM) g_h[0][i] = 0.0f;
    if (i < ROWS)       out[i] = bv[0];   // out has BS*T*A = 131072 elements
}

// ---------------------------------------------------------------------------
// gemm1: g_x[r][c] = relu( obs_row(r) . W1[c] + b1[c] ),  r=(t,n), K=128
// obs layout [bs][t][a][d]; row r -> t=r>>10, n=r&1023, bs=n>>3, a=n&7
// ---------------------------------------------------------------------------
__global__ __launch_bounds__(256, 2) void gemm1_kernel(
    const float* __restrict__ obs, const float* __restrict__ W1,
    const float* __restrict__ b1)
{
    __shared__ float As[16][132];
    __shared__ float Bs[16][132];
    const int tid = threadIdx.x;
    const int tx = tid & 15, ty = tid >> 4;
    const int row0 = blockIdx.y * 128;
    const int col0 = blockIdx.x * 128;

    float acc[8][8] = {};

    for (int k0 = 0; k0 < D_IN; k0 += 16) {
#pragma unroll
        for (int i = 0; i < 2; i++) {
            int idx = tid + i * 256;        // 0..511 : 128 rows x 4 float4
            int row = idx >> 2;
            int kq  = (idx & 3) << 2;
            int r = row0 + row;
            int t = r >> 10;
            int n = r & 1023;
            size_t off = (size_t)(n >> 3) * 131072 + (size_t)t * 1024 + (size_t)(n & 7) * 128;
            float4 v = *(const float4*)(obs + off + k0 + kq);
            As[kq + 0][row] = v.x; As[kq + 1][row] = v.y;
            As[kq + 2][row] = v.z; As[kq + 3][row] = v.w;
        }
#pragma unroll
        for (int i = 0; i < 2; i++) {
            int idx = tid + i * 256;
            int row = idx >> 2;
            int kq  = (idx & 3) << 2;
            float4 v = *(const float4*)(W1 + (size_t)(col0 + row) * D_IN + k0 + kq);
            Bs[kq + 0][row] = v.x; Bs[kq + 1][row] = v.y;
            Bs[kq + 2][row] = v.z; Bs[kq + 3][row] = v.w;
        }
        __syncthreads();
#pragma unroll
        for (int k = 0; k < 16; k++) {
            float a[8], b[8];
            *(float4*)(a)     = *(const float4*)&As[k][ty * 8];
            *(float4*)(a + 4) = *(const float4*)&As[k][ty * 8 + 4];
            *(float4*)(b)     = *(const float4*)&Bs[k][tx * 8];
            *(float4*)(b + 4) = *(const float4*)&Bs[k][tx * 8 + 4];
#pragma unroll
            for (int i = 0; i < 8; i++)
#pragma unroll
                for (int j = 0; j < 8; j++)
                    acc[i][j] = fmaf(a[i], b[j], acc[i][j]);
        }
        __syncthreads();
    }

#pragma unroll
    for (int i = 0; i < 8; i++) {
        int r = row0 + ty * 8 + i;
        float* dst = g_x + (size_t)r * H_DIM + col0 + tx * 8;
#pragma unroll
        for (int j = 0; j < 8; j += 4) {
            float4 v;
            v.x = fmaxf(acc[i][j + 0] + b1[col0 + tx * 8 + j + 0], 0.0f);
            v.y = fmaxf(acc[i][j + 1] + b1[col0 + tx * 8 + j + 1], 0.0f);
            v.z = fmaxf(acc[i][j + 2] + b1[col0 + tx * 8 + j + 2], 0.0f);
            v.w = fmaxf(acc[i][j + 3] + b1[col0 + tx * 8 + j + 3], 0.0f);
            *(float4*)(dst + j) = v;
        }
    }
}

// ---------------------------------------------------------------------------
// gemm2: g_gi[r][c] = g_x[r] . W_ih[c] + b_ih[c],  K=512, Ncol=1536
// ---------------------------------------------------------------------------
__global__ __launch_bounds__(256, 2) void gemm2_kernel(
    const float* __restrict__ W_ih, const float* __restrict__ b_ih)
{
    __shared__ float As[16][132];
    __shared__ float Bs[16][132];
    const int tid = threadIdx.x;
    const int tx = tid & 15, ty = tid >> 4;
    const int row0 = blockIdx.y * 128;
    const int col0 = blockIdx.x * 128;

    float acc[8][8] = {};

    for (int k0 = 0; k0 < H_DIM; k0 += 16) {
#pragma unroll
        for (int i = 0; i < 2; i++) {
            int idx = tid + i * 256;
            int row = idx >> 2;
            int kq  = (idx & 3) << 2;
            float4 v = *(const float4*)(g_x + (size_t)(row0 + row) * H_DIM + k0 + kq);
            As[kq + 0][row] = v.x; As[kq + 1][row] = v.y;
            As[kq + 2][row] = v.z; As[kq + 3][row] = v.w;
        }
#pragma unroll
        for (int i = 0; i < 2; i++) {
            int idx = tid + i * 256;
            int row = idx >> 2;
            int kq  = (idx & 3) << 2;
            float4 v = *(const float4*)(W_ih + (size_t)(col0 + row) * H_DIM + k0 + kq);
            Bs[kq + 0][row] = v.x; Bs[kq + 1][row] = v.y;
            Bs[kq + 2][row] = v.z; Bs[kq + 3][row] = v.w;
        }
        __syncthreads();
#pragma unroll
        for (int k = 0; k < 16; k++) {
            float a[8], b[8];
            *(float4*)(a)     = *(const float4*)&As[k][ty * 8];
            *(float4*)(a + 4) = *(const float4*)&As[k][ty * 8 + 4];
            *(float4*)(b)     = *(const float4*)&Bs[k][tx * 8];
            *(float4*)(b + 4) = *(const float4*)&Bs[k][tx * 8 + 4];
#pragma unroll
            for (int i = 0; i < 8; i++)
#pragma unroll
                for (int j = 0; j < 8; j++)
                    acc[i][j] = fmaf(a[i], b[j], acc[i][j]);
        }
        __syncthreads();
    }

#pragma unroll
    for (int i = 0; i < 8; i++) {
        int r = row0 + ty * 8 + i;
        float* dst = g_gi + (size_t)r * G_DIM + col0 + tx * 8;
#pragma unroll
        for (int j = 0; j < 8; j += 4) {
            float4 v;
            v.x = acc[i][j + 0] + b_ih[col0 + tx * 8 + j + 0];
            v.y = acc[i][j + 1] + b_ih[col0 + tx * 8 + j + 1];
            v.z = acc[i][j + 2] + b_ih[col0 + tx * 8 + j + 2];
            v.w = acc[i][j + 3] + b_ih[col0 + tx * 8 + j + 3];
            *(float4*)(dst + j) = v;
        }
    }
}

// ---------------------------------------------------------------------------
// gru_step: one timestep. Each CTA computes gh rows {j0..j0+31, +512, +1024}
// for a 128-wide n tile (96x128 output, K=512), then fuses gate math,
// h update, and the value head (partial dot -> atomicAdd into out).
// Grid: (16 j-tiles, 8 n-tiles), 256 threads.
// ---------------------------------------------------------------------------
__global__ __launch_bounds__(256, 1) void gru_step_kernel(
    const float* __restrict__ W_hh, const float* __restrict__ b_hh,
    const float* __restrict__ Wv,  float* __restrict__ out, int t)
{
    __shared__ float As[16][100];   // 96 rows (+4 pad)
    __shared__ float Bs[16][132];   // 128 cols (+4 pad)
    __shared__ float s_v[16][128];

    const int tid = threadIdx.x;
    const int tx = tid & 15, ty = tid >> 4;
    const int j0 = blockIdx.x * 32;
    const int n0 = blockIdx.y * 128;

    const float* h_prev = g_h[t & 1];
    float*       h_next = g_h[(t + 1) & 1];
    const float* gi_t   = g_gi + (size_t)t * NB * G_DIM;

    float acc[3][2][8] = {};

    for (int k0 = 0; k0 < H_DIM; k0 += 16) {
        // A tile: 96 rows x 16 k = 384 float4
        for (int i = tid; i < 384; i += 256) {
            int row = i >> 2;
            int kq  = (i & 3) << 2;
            int g   = row >> 5;          // gate 0=r,1=z,2=n
            int jl  = row & 31;
            float4 v = *(const float4*)(W_hh + (size_t)(g * 512 + j0 + jl) * H_DIM + k0 + kq);
            As[kq + 0][row] = v.x; As[kq + 1][row] = v.y;
            As[kq + 2][row] = v.z; As[kq + 3][row] = v.w;
        }
        // B tile: h_prev, 128 rows x 16 k
#pragma unroll
        for (int i = 0; i < 2; i++) {
            int idx = tid + i * 256;
            int row = idx >> 2;
            int kq  = (idx & 3) << 2;
            float4 v = *(const float4*)(h_prev + (size_t)(n0 + row) * H_DIM + k0 + kq);
            Bs[kq + 0][row] = v.x; Bs[kq + 1][row] = v.y;
            Bs[kq + 2][row] = v.z; Bs[kq + 3][row] = v.w;
        }
        __syncthreads();
#pragma unroll
        for (int k = 0; k < 16; k++) {
            float2 ar = *(const float2*)&As[k][ty * 2];
            float2 az = *(const float2*)&As[k][32 + ty * 2];
            float2 an = *(const float2*)&As[k][64 + ty * 2];
            float b[8];
            *(float4*)(b)     = *(const float4*)&Bs[k][tx * 8];
            *(float4*)(b + 4) = *(const float4*)&Bs[k][tx * 8 + 4];
#pragma unroll
            for (int nn = 0; nn < 8; nn++) {
                acc[0][0][nn] = fmaf(ar.x, b[nn], acc[0][0][nn]);
                acc[0][1][nn] = fmaf(ar.y, b[nn], acc[0][1][nn]);
                acc[1][0][nn] = fmaf(az.x, b[nn], acc[1][0][nn]);
                acc[1][1][nn] = fmaf(az.y, b[nn], acc[1][1][nn]);
                acc[2][0][nn] = fmaf(an.x, b[nn], acc[2][0][nn]);
                acc[2][1][nn] = fmaf(an.y, b[nn], acc[2][1][nn]);
            }
        }
        __syncthreads();
    }

    // Epilogue: gates + h update + value-head partial
    const int jb = j0 + ty * 2;
    float2 bhr = *(const float2*)&b_hh[jb];
    float2 bhz = *(const float2*)&b_hh[512 + jb];
    float2 bhn = *(const float2*)&b_hh[1024 + jb];
    float2 wv2 = *(const float2*)&Wv[jb];
    float vs[8];

#pragma unroll
    for (int nn = 0; nn < 8; nn++) {
        int n_g = n0 + tx * 8 + nn;
        const float* gi = gi_t + (size_t)n_g * G_DIM + jb;
        float2 gr = *(const float2*)(gi);
        float2 gz = *(const float2*)(gi + 512);
        float2 gn = *(const float2*)(gi + 1024);
        float2 hp = *(const float2*)(h_prev + (size_t)n_g * H_DIM + jb);

        float r0 = sigf(gr.x + bhr.x + acc[0][0][nn]);
        float r1 = sigf(gr.y + bhr.y + acc[0][1][nn]);
        float z0 = sigf(gz.x + bhz.x + acc[1][0][nn]);
        float z1 = sigf(gz.y + bhz.y + acc[1][1][nn]);
        float hn0 = acc[2][0][nn] + bhn.x;
        float hn1 = acc[2][1][nn] + bhn.y;
        float nt0 = tanhf(gn.x + r0 * hn0);
        float nt1 = tanhf(gn.y + r1 * hn1);
        float h0 = (1.0f - z0) * nt0 + z0 * hp.x;
        float h1 = (1.0f - z1) * nt1 + z1 * hp.y;
        float2 hw; hw.x = h0; hw.y = h1;
        *(float2*)(h_next + (size_t)n_g * H_DIM + jb) = hw;
        vs[nn] = wv2.x * h0 + wv2.y * h1;
    }

    // reduce value-head partials over ty (32 j's per CTA), one atomic per n
#pragma unroll
    for (int nn = 0; nn < 8; nn++) s_v[ty][tx * 8 + nn] = vs[nn];
    __syncthreads();
    if (tid < 128) {
        float s = 0.0f;
#pragma unroll
        for (int q = 0; q < 16; q++) s += s_v[q][tid];
        int n_g = n0 + tid;
        int bs = n_g >> 3, a = n_g & 7;
        atomicAdd(&out[((size_t)bs * T_LEN + t) * 8 + a], s);
    }
}

// ---------------------------------------------------------------------------
extern "C" void kernel_launch(void* const* d_in, const int* in_sizes, int n_in,
                              void* d_out, int out_size)
{
    const float* obs  = (const float*)d_in[0];
    const float* W1   = (const float*)d_in[1];
    const float* b1   = (const float*)d_in[2];
    const float* W_ih = (const float*)d_in[3];
    const float* b_ih = (const float*)d_in[4];
    const float* W_hh = (const float*)d_in[5];
    const float* b_hh = (const float*)d_in[6];
    const float* Wv   = (const float*)d_in[7];
    const float* bv   = (const float*)d_in[8];
    float* out = (float*)d_out;

    init_kernel<<<2048, 256>>>(out, bv);
    gemm1_kernel<<<dim3(4, 1024), 256>>>(obs, W1, b1);
    gemm2_kernel<<<dim3(12, 1024), 256>>>(W_ih, b_ih);
    for (int t = 0; t < T_LEN; t++)
        gru_step_kernel<<<dim3(16, 8), 256>>>(W_hh, b_hh, Wv, out, t);
}

// round 3
// speedup vs baseline: 2.1103x; 2.1103x over previous
#include <cuda_runtime.h>
#include <cuda_bf16.h>
#include <math.h>
#include <stdint.h>

#define T_LEN 128
#define NB    1024
#define D_IN  128
#define H_DIM 512
#define G_DIM 1536
#define ROWS  (T_LEN * NB)     // 131072

// ---------------- scratch (__device__ globals) ------------------------------
__device__ __nv_bfloat16 g_xh[(size_t)ROWS * H_DIM];   // fc1 out hi
__device__ __nv_bfloat16 g_xl[(size_t)ROWS * H_DIM];   // fc1 out lo
__device__ float         g_gi[(size_t)ROWS * G_DIM];   // input-gate preacts
__device__ float         g_hf[2][NB * H_DIM];          // fp32 h ping-pong
__device__ __nv_bfloat16 g_Ah[2][NB * H_DIM];          // h hi ping-pong
__device__ __nv_bfloat16 g_Al[2][NB * H_DIM];          // h lo ping-pong
__device__ __nv_bfloat16 g_Wih_h[G_DIM * H_DIM];       // W_ih hi (row-major)
__device__ __nv_bfloat16 g_Wih_l[G_DIM * H_DIM];
__device__ __nv_bfloat16 g_Whh_h[G_DIM * H_DIM];       // W_hh hi (gate-triple reorder)
__device__ __nv_bfloat16 g_Whh_l[G_DIM * H_DIM];

__device__ __forceinline__ float sigf(float x) { return 1.0f / (1.0f + expf(-x)); }

#define SW128(off) ((off) ^ (((off) >> 3) & 0x70))

__device__ __forceinline__ uint32_t smem_u32(const void* p) {
    uint32_t a;
    asm("{ .reg .u64 t; cvta.to.shared.u64 t, %1; cvt.u32.u64 %0, t; }" : "=r"(a) : "l"(p));
    return a;
}
__device__ __forceinline__ void cpasync16(uint32_t dst, const void* src) {
    asm volatile("cp.async.ca.shared.global [%0], [%1], 16;" :: "r"(dst), "l"(src));
}
#define CP_COMMIT() asm volatile("cp.async.commit_group;" ::: "memory")
#define CP_WAIT1()  asm volatile("cp.async.wait_group 1;" ::: "memory")
#define CP_WAIT0()  asm volatile("cp.async.wait_group 0;" ::: "memory")

__device__ __forceinline__ void ldsm4(uint32_t (&r)[4], uint32_t addr) {
    asm volatile("ldmatrix.sync.aligned.m8n8.x4.shared.b16 {%0,%1,%2,%3}, [%4];"
        : "=r"(r[0]), "=r"(r[1]), "=r"(r[2]), "=r"(r[3]) : "r"(addr));
}
__device__ __forceinline__ void mma16816(float (&c)[4], const uint32_t (&a)[4],
                                         uint32_t b0, uint32_t b1) {
    asm volatile(
        "mma.sync.aligned.m16n8k16.row.col.f32.bf16.bf16.f32 "
        "{%0,%1,%2,%3}, {%4,%5,%6,%7}, {%8,%9}, {%0,%1,%2,%3};"
        : "+f"(c[0]), "+f"(c[1]), "+f"(c[2]), "+f"(c[3])
        : "r"(a[0]), "r"(a[1]), "r"(a[2]), "r"(a[3]), "r"(b0), "r"(b1));
}

// ---------------- init ------------------------------------------------------
__global__ void init_kernel(float* __restrict__ out, const float* __restrict__ bv) {
    int i = blockIdx.x * blockDim.x + threadIdx.x;   // 524288 threads
    if (i < NB * H_DIM) g_hf[0][i] = 0.0f;
    if (i < NB * H_DIM / 2) {
        ((uint32_t*)g_Ah[0])[i] = 0u;
        ((uint32_t*)g_Al[0])[i] = 0u;
    }
    if (i < ROWS) out[i] = bv[0];
}

// ---------------- prep: split W_ih / reorder+split W_hh ---------------------
__global__ void prep_kernel(const float* __restrict__ W_ih, const float* __restrict__ W_hh) {
    int idx = blockIdx.x * blockDim.x + threadIdx.x;   // 786432
    if (idx >= G_DIM * H_DIM) return;
    // W_ih straight split
    {
        float v = W_ih[idx];
        __nv_bfloat16 hi = __float2bfloat16(v);
        g_Wih_h[idx] = hi;
        g_Wih_l[idx] = __float2bfloat16(v - __bfloat162float(hi));
    }
    // W_hh gate-triple reorder: dest row jtr = jc*96 + gt*32 + jl
    {
        int jtr = idx >> 9, k = idx & 511;
        int jc = jtr / 96, rem = jtr % 96;
        int gt = rem >> 5, jl = rem & 31;
        float v = W_hh[(size_t)(gt * 512 + jc * 32 + jl) * H_DIM + k];
        __nv_bfloat16 hi = __float2bfloat16(v);
        g_Whh_h[idx] = hi;
        g_Whh_l[idx] = __float2bfloat16(v - __bfloat162float(hi));
    }
}

// ---------------- gemm1: x = relu(obs @ W1^T + b1) -> bf16 hi/lo -------------
__global__ __launch_bounds__(256, 2) void gemm1_kernel(
    const float* __restrict__ obs, const float* __restrict__ W1,
    const float* __restrict__ b1)
{
    __shared__ float As[16][132];
    __shared__ float Bs[16][132];
    const int tid = threadIdx.x;
    const int tx = tid & 15, ty = tid >> 4;
    const int row0 = blockIdx.y * 128;
    const int col0 = blockIdx.x * 128;

    float acc[8][8] = {};

    for (int k0 = 0; k0 < D_IN; k0 += 16) {
#pragma unroll
        for (int i = 0; i < 2; i++) {
            int idx = tid + i * 256;
            int row = idx >> 2;
            int kq  = (idx & 3) << 2;
            int r = row0 + row;
            int t = r >> 10;
            int n = r & 1023;
            size_t off = (size_t)(n >> 3) * 131072 + (size_t)t * 1024 + (size_t)(n & 7) * 128;
            float4 v = *(const float4*)(obs + off + k0 + kq);
            As[kq + 0][row] = v.x; As[kq + 1][row] = v.y;
            As[kq + 2][row] = v.z; As[kq + 3][row] = v.w;
        }
#pragma unroll
        for (int i = 0; i < 2; i++) {
            int idx = tid + i * 256;
            int row = idx >> 2;
            int kq  = (idx & 3) << 2;
            float4 v = *(const float4*)(W1 + (size_t)(col0 + row) * D_IN + k0 + kq);
            Bs[kq + 0][row] = v.x; Bs[kq + 1][row] = v.y;
            Bs[kq + 2][row] = v.z; Bs[kq + 3][row] = v.w;
        }
        __syncthreads();
#pragma unroll
        for (int k = 0; k < 16; k++) {
            float a[8], b[8];
            *(float4*)(a)     = *(const float4*)&As[k][ty * 8];
            *(float4*)(a + 4) = *(const float4*)&As[k][ty * 8 + 4];
            *(float4*)(b)     = *(const float4*)&Bs[k][tx * 8];
            *(float4*)(b + 4) = *(const float4*)&Bs[k][tx * 8 + 4];
#pragma unroll
            for (int i = 0; i < 8; i++)
#pragma unroll
                for (int j = 0; j < 8; j++)
                    acc[i][j] = fmaf(a[i], b[j], acc[i][j]);
        }
        __syncthreads();
    }

#pragma unroll
    for (int i = 0; i < 8; i++) {
        int r = row0 + ty * 8 + i;
        size_t base = (size_t)r * H_DIM + col0 + tx * 8;
#pragma unroll
        for (int j = 0; j < 8; j += 2) {
            float v0 = fmaxf(acc[i][j + 0] + b1[col0 + tx * 8 + j + 0], 0.0f);
            float v1 = fmaxf(acc[i][j + 1] + b1[col0 + tx * 8 + j + 1], 0.0f);
            __nv_bfloat16 h0 = __float2bfloat16(v0);
            __nv_bfloat16 h1 = __float2bfloat16(v1);
            __nv_bfloat16 l0 = __float2bfloat16(v0 - __bfloat162float(h0));
            __nv_bfloat16 l1 = __float2bfloat16(v1 - __bfloat162float(h1));
            uint32_t ph = (uint32_t)__bfloat16_as_ushort(h0) | ((uint32_t)__bfloat16_as_ushort(h1) << 16);
            uint32_t pl = (uint32_t)__bfloat16_as_ushort(l0) | ((uint32_t)__bfloat16_as_ushort(l1) << 16);
            *(uint32_t*)(g_xh + base + j) = ph;
            *(uint32_t*)(g_xl + base + j) = pl;
        }
    }
}

// ---------------- gemm2: gi = x @ W_ih^T + b_ih  (bf16x3 mma.sync) ----------
// CTA 128m x 128n, 8 warps (4m x 2n), K-extended 24 chunks of 64.
// SMEM: A buf 16KB x2 @0/16384, B buf 16KB x2 @32768/49152 = 64KB
__global__ __launch_bounds__(256, 1) void gemm2_kernel(const float* __restrict__ b_ih)
{
    extern __shared__ char smem[];
    const uint32_t sb = smem_u32(smem);
    const int tid = threadIdx.x;
    const int wid = tid >> 5, lane = tid & 31;
    const int mw = wid >> 1, nw = wid & 1;
    const int n0 = blockIdx.x * 128;
    const int r0 = blockIdx.y * 128;

    float c[2][8][4] = {};

    const uint32_t sbA[2] = {sb, sb + 16384};
    const uint32_t sbB[2] = {sb + 32768, sb + 49152};

    auto load_chunk = [&](int ch, int buf) {
        int v = ch >> 3;
        int kk = (ch & 7) * 64;
        const __nv_bfloat16* Asrc = (v == 1) ? g_xl : g_xh;
        const __nv_bfloat16* Bsrc = (v == 2) ? g_Wih_l : g_Wih_h;
#pragma unroll
        for (int i = 0; i < 4; i++) {
            int idx = tid + i * 256;
            int row = idx >> 3, s = idx & 7;
            cpasync16(sbA[buf] + SW128((uint32_t)(row * 128 + s * 16)),
                      Asrc + (size_t)(r0 + row) * H_DIM + kk + s * 8);
        }
#pragma unroll
        for (int i = 0; i < 4; i++) {
            int idx = tid + i * 256;
            int row = idx >> 3, s = idx & 7;
            cpasync16(sbB[buf] + SW128((uint32_t)(row * 128 + s * 16)),
                      Bsrc + (size_t)(n0 + row) * H_DIM + kk + s * 8);
        }
    };

    load_chunk(0, 0);
    CP_COMMIT();

    for (int ch = 0; ch < 24; ch++) {
        if (ch < 23) { load_chunk(ch + 1, (ch + 1) & 1); CP_COMMIT(); CP_WAIT1(); }
        else CP_WAIT0();
        __syncthreads();
        const uint32_t sA = sbA[ch & 1], sB = sbB[ch & 1];
#pragma unroll
        for (int ks = 0; ks < 4; ks++) {
            uint32_t a[2][4];
#pragma unroll
            for (int mi = 0; mi < 2; mi++) {
                uint32_t arow = mw * 32 + mi * 16 + (lane & 15);
                uint32_t acol = ks * 16 + ((lane >> 4) << 3);
                ldsm4(a[mi], sA + SW128(arow * 128 + acol * 2));
            }
#pragma unroll
            for (int bp = 0; bp < 4; bp++) {
                uint32_t b[4];
                uint32_t brow = nw * 64 + bp * 16 + (lane & 7) + ((lane >> 4) & 1) * 8;
                uint32_t bcol = ks * 16 + ((lane >> 3) & 1) * 8;
                ldsm4(b, sB + SW128(brow * 128 + bcol * 2));
#pragma unroll
                for (int mi = 0; mi < 2; mi++) {
                    mma16816(c[mi][2 * bp],     a[mi], b[0], b[1]);
                    mma16816(c[mi][2 * bp + 1], a[mi], b[2], b[3]);
                }
            }
        }
        __syncthreads();
    }

    // epilogue
    const int g = lane >> 2, ct = lane & 3;
#pragma unroll
    for (int mi = 0; mi < 2; mi++) {
#pragma unroll
        for (int nt = 0; nt < 8; nt++) {
            int m = r0 + mw * 32 + mi * 16 + g;
            int n = n0 + nw * 64 + nt * 8 + ct * 2;
            float2 bi = *(const float2*)(b_ih + n);
            float2 v0, v1;
            v0.x = c[mi][nt][0] + bi.x; v0.y = c[mi][nt][1] + bi.y;
            v1.x = c[mi][nt][2] + bi.x; v1.y = c[mi][nt][3] + bi.y;
            *(float2*)(g_gi + (size_t)m * G_DIM + n)       = v0;
            *(float2*)(g_gi + (size_t)(m + 8) * G_DIM + n) = v1;
        }
    }
}

// ---------------- gru step: gh = h @ W_hh^T (bf16x3) + fused epilogue -------
// grid (16 jc, 8 mt) = 128 CTAs. CTA: 128 m x 96 triple-rows (3 gates x 32 j).
// 8 warps, each 16 m x 96 rows. K-extended 24 chunks of 64.
// SMEM: A 16KB x2 @0/16384, B 12KB x2 @32768/45056 = 56KB
__global__ __launch_bounds__(256, 1) void gru_step_kernel(
    const float* __restrict__ b_hh, const float* __restrict__ Wv,
    float* __restrict__ out, int t)
{
    extern __shared__ char smem[];
    const uint32_t sb = smem_u32(smem);
    const int tid = threadIdx.x;
    const int wid = tid >> 5, lane = tid & 31;
    const int jc = blockIdx.x;    // 0..15
    const int mt = blockIdx.y;    // 0..7
    const int rd = t & 1, wr = (t + 1) & 1;

    float c[12][4] = {};

    const uint32_t sbA[2] = {sb, sb + 16384};
    const uint32_t sbB[2] = {sb + 32768, sb + 45056};

    auto load_chunk = [&](int ch, int buf) {
        int v = ch >> 3;
        int kk = (ch & 7) * 64;
        const __nv_bfloat16* Asrc = (v == 1) ? g_Al[rd] : g_Ah[rd];
        const __nv_bfloat16* Bsrc = (v == 2) ? g_Whh_l : g_Whh_h;
#pragma unroll
        for (int i = 0; i < 4; i++) {
            int idx = tid + i * 256;
            int row = idx >> 3, s = idx & 7;
            cpasync16(sbA[buf] + SW128((uint32_t)(row * 128 + s * 16)),
                      Asrc + (size_t)(mt * 128 + row) * H_DIM + kk + s * 8);
        }
#pragma unroll
        for (int i = 0; i < 3; i++) {
            int idx = tid + i * 256;
            int row = idx >> 3, s = idx & 7;
            cpasync16(sbB[buf] + SW128((uint32_t)(row * 128 + s * 16)),
                      Bsrc + (size_t)(jc * 96 + row) * H_DIM + kk + s * 8);
        }
    };

    load_chunk(0, 0);
    CP_COMMIT();

    for (int ch = 0; ch < 24; ch++) {
        if (ch < 23) { load_chunk(ch + 1, (ch + 1) & 1); CP_COMMIT(); CP_WAIT1(); }
        else CP_WAIT0();
        __syncthreads();
        const uint32_t sA = sbA[ch & 1], sB = sbB[ch & 1];
#pragma unroll
        for (int ks = 0; ks < 4; ks++) {
            uint32_t a[4];
            uint32_t arow = wid * 16 + (lane & 15);
            uint32_t acol = ks * 16 + ((lane >> 4) << 3);
            ldsm4(a, sA + SW128(arow * 128 + acol * 2));
#pragma unroll
            for (int bt = 0; bt < 6; bt++) {
                uint32_t b[4];
                uint32_t brow = bt * 16 + (lane & 7) + ((lane >> 4) & 1) * 8;
                uint32_t bcol = ks * 16 + ((lane >> 3) & 1) * 8;
                ldsm4(b, sB + SW128(brow * 128 + bcol * 2));
                mma16816(c[2 * bt],     a, b[0], b[1]);
                mma16816(c[2 * bt + 1], a, b[2], b[3]);
            }
        }
        __syncthreads();
    }

    // ---------------- fused epilogue ----------------
    const int g = lane >> 2, ct = lane & 3;
    const int j_base = jc * 32;

#pragma unroll
    for (int mi = 0; mi < 2; mi++) {
        int m_g = mt * 128 + wid * 16 + g + mi * 8;
        const float* gi_row = g_gi + ((size_t)t * NB + m_g) * G_DIM + j_base;
        const float* hp_row = g_hf[rd] + (size_t)m_g * H_DIM + j_base;
        float*       hn_row = g_hf[wr] + (size_t)m_g * H_DIM + j_base;
        __nv_bfloat16* ah_row = g_Ah[wr] + (size_t)m_g * H_DIM + j_base;
        __nv_bfloat16* al_row = g_Al[wr] + (size_t)m_g * H_DIM + j_base;

        float vp = 0.0f;
#pragma unroll
        for (int jj = 0; jj < 4; jj++) {
            int jl = jj * 8 + ct * 2;
            int j  = j_base + jl;
            float2 gr = *(const float2*)(gi_row + jl);
            float2 gz = *(const float2*)(gi_row + 512 + jl);
            float2 gn = *(const float2*)(gi_row + 1024 + jl);
            float2 br = *(const float2*)(b_hh + j);
            float2 bz = *(const float2*)(b_hh + 512 + j);
            float2 bn = *(const float2*)(b_hh + 1024 + j);
            float2 hp = *(const float2*)(hp_row + jl);
            float2 wv = *(const float2*)(Wv + j);

            float cr0 = c[jj][mi * 2], cr1 = c[jj][mi * 2 + 1];
            float cz0 = c[4 + jj][mi * 2], cz1 = c[4 + jj][mi * 2 + 1];
            float cn0 = c[8 + jj][mi * 2], cn1 = c[8 + jj][mi * 2 + 1];

            float r0 = sigf(gr.x + br.x + cr0);
            float r1 = sigf(gr.y + br.y + cr1);
            float z0 = sigf(gz.x + bz.x + cz0);
            float z1 = sigf(gz.y + bz.y + cz1);
            float nt0 = tanhf(gn.x + r0 * (cn0 + bn.x));
            float nt1 = tanhf(gn.y + r1 * (cn1 + bn.y));
            float h0 = (1.0f - z0) * nt0 + z0 * hp.x;
            float h1 = (1.0f - z1) * nt1 + z1 * hp.y;

            float2 hw; hw.x = h0; hw.y = h1;
            *(float2*)(hn_row + jl) = hw;

            __nv_bfloat16 hh0 = __float2bfloat16(h0);
            __nv_bfloat16 hh1 = __float2bfloat16(h1);
            __nv_bfloat16 ll0 = __float2bfloat16(h0 - __bfloat162float(hh0));
            __nv_bfloat16 ll1 = __float2bfloat16(h1 - __bfloat162float(hh1));
            uint32_t ph = (uint32_t)__bfloat16_as_ushort(hh0) | ((uint32_t)__bfloat16_as_ushort(hh1) << 16);
            uint32_t pl = (uint32_t)__bfloat16_as_ushort(ll0) | ((uint32_t)__bfloat16_as_ushort(ll1) << 16);
            *(uint32_t*)(ah_row + jl) = ph;
            *(uint32_t*)(al_row + jl) = pl;

            vp = fmaf(wv.x, h0, vp);
            vp = fmaf(wv.y, h1, vp);
        }
        // reduce over the 4 ct lanes (j columns), one atomic per (m, CTA)
        vp += __shfl_xor_sync(0xffffffffu, vp, 1);
        vp += __shfl_xor_sync(0xffffffffu, vp, 2);
        if (ct == 0) {
            int bs = m_g >> 3, a = m_g & 7;
            atomicAdd(&out[((size_t)bs * T_LEN + t) * 8 + a], vp);
        }
    }
}

// ---------------------------------------------------------------------------
extern "C" void kernel_launch(void* const* d_in, const int* in_sizes, int n_in,
                              void* d_out, int out_size)
{
    const float* obs  = (const float*)d_in[0];
    const float* W1   = (const float*)d_in[1];
    const float* b1   = (const float*)d_in[2];
    const float* W_ih = (const float*)d_in[3];
    const float* b_ih = (const float*)d_in[4];
    const float* W_hh = (const float*)d_in[5];
    const float* b_hh = (const float*)d_in[6];
    const float* Wv   = (const float*)d_in[7];
    const float* bv   = (const float*)d_in[8];
    float* out = (float*)d_out;

    cudaFuncSetAttribute(gemm2_kernel,    cudaFuncAttributeMaxDynamicSharedMemorySize, 65536);
    cudaFuncSetAttribute(gru_step_kernel, cudaFuncAttributeMaxDynamicSharedMemorySize, 57344);

    init_kernel<<<2048, 256>>>(out, bv);
    prep_kernel<<<3072, 256>>>(W_ih, W_hh);
    gemm1_kernel<<<dim3(4, 1024), 256>>>(obs, W1, b1);
    gemm2_kernel<<<dim3(12, 1024), 256, 65536>>>(b_ih);
    for (int t = 0; t < T_LEN; t++)
        gru_step_kernel<<<dim3(16, 8), 256, 57344>>>(b_hh, Wv, out, t);
}

// round 4
// speedup vs baseline: 3.2771x; 1.5530x over previous
#include <cuda_runtime.h>
#include <cuda_bf16.h>
#include <math.h>
#include <stdint.h>

#define T_LEN 128
#define NB    1024
#define D_IN  128
#define H_DIM 512
#define G_DIM 1536
#define ROWS  (T_LEN * NB)     // 131072

// ---------------- scratch (__device__ globals) ------------------------------
// Tile-contiguous, pre-swizzled (SW128) bf16 operand storage.
// x tiles:   [hl][rt 1024][kt 8] tiles of 128x64  (16KB each)
__device__ __nv_bfloat16 g_xT[2][1024][8][8192];
// W_ih tiles:[hl][nt 12][kt 8] tiles of 128x64
__device__ __nv_bfloat16 g_WihT[2][12][8][8192];
// W_hh tiles (gate-triple reorder): [hl][jc 16][kt 8] tiles of 96x64 (12KB)
__device__ __nv_bfloat16 g_WhhT[2][16][8][6144];
// h tiles ping-pong: [pp][hl][mt 8][kt 8] tiles of 128x64
__device__ __nv_bfloat16 g_AT[2][2][8][8][8192];
__device__ float g_gi[(size_t)ROWS * G_DIM];
__device__ float g_hf[2][NB * H_DIM];

__device__ __forceinline__ float sigf(float x) { return 1.0f / (1.0f + expf(-x)); }

#define SW128(off) ((off) ^ (((off) >> 3) & 0x70))

__device__ __forceinline__ uint32_t smem_u32(const void* p) {
    uint32_t a;
    asm("{ .reg .u64 t; cvta.to.shared.u64 t, %1; cvt.u32.u64 %0, t; }" : "=r"(a) : "l"(p));
    return a;
}

#define MBAR_INIT(addr, cnt) \
    asm volatile("mbarrier.init.shared.b64 [%0], %1;" :: "r"(addr), "r"(cnt) : "memory")
#define MBAR_EXPECT(addr, bytes) \
    asm volatile("mbarrier.arrive.expect_tx.shared.b64 _, [%0], %1;" :: "r"(addr), "r"(bytes) : "memory")
#define FENCE_ASYNC() asm volatile("fence.proxy.async.shared::cta;" ::: "memory")

#define MBAR_WAIT_PARITY(addr, par) do {                                        \
    uint32_t _m = (addr); uint32_t _p = (par); uint32_t _d;                     \
    asm volatile("{\n\t.reg .pred p;\n\t"                                       \
        "mbarrier.try_wait.parity.acquire.cta.shared::cta.b64 p, [%1], %2;\n\t" \
        "selp.b32 %0, 1, 0, p;\n\t}" : "=r"(_d) : "r"(_m), "r"(_p) : "memory"); \
    if (!_d) {                                                                  \
        asm volatile("{\n\t.reg .pred P1;\n\t"                                  \
        "WL_%=:\n\t"                                                            \
        "mbarrier.try_wait.parity.acquire.cta.shared::cta.b64 P1, [%0], %1, 0x989680;\n\t" \
        "@P1 bra.uni WD_%=;\n\t"                                                \
        "bra.uni WL_%=;\n\t"                                                    \
        "WD_%=:\n\t}" :: "r"(_m), "r"(_p) : "memory");                          \
    }                                                                           \
} while (0)

#define BULK_G2S(dst, src, bytes, mbar) \
    asm volatile("cp.async.bulk.shared::cta.global.mbarrier::complete_tx::bytes [%0], [%1], %2, [%3];" \
        :: "r"(dst), "l"(src), "r"((uint32_t)(bytes)), "r"(mbar) : "memory")

__device__ __forceinline__ void ldsm4(uint32_t (&r)[4], uint32_t addr) {
    asm volatile("ldmatrix.sync.aligned.m8n8.x4.shared.b16 {%0,%1,%2,%3}, [%4];"
        : "=r"(r[0]), "=r"(r[1]), "=r"(r[2]), "=r"(r[3]) : "r"(addr));
}
__device__ __forceinline__ void mma16816(float (&c)[4], const uint32_t (&a)[4],
                                         uint32_t b0, uint32_t b1) {
    asm volatile(
        "mma.sync.aligned.m16n8k16.row.col.f32.bf16.bf16.f32 "
        "{%0,%1,%2,%3}, {%4,%5,%6,%7}, {%8,%9}, {%0,%1,%2,%3};"
        : "+f"(c[0]), "+f"(c[1]), "+f"(c[2]), "+f"(c[3])
        : "r"(a[0]), "r"(a[1]), "r"(a[2]), "r"(a[3]), "r"(b0), "r"(b1));
}

// ---------------- init ------------------------------------------------------
__global__ void init_kernel(float* __restrict__ out, const float* __restrict__ bv) {
    int i = blockIdx.x * blockDim.x + threadIdx.x;   // 524288 threads
    if (i < NB * H_DIM) g_hf[0][i] = 0.0f;
    if (i < 524288) ((uint32_t*)g_AT[0])[i] = 0u;    // zero h0 hi/lo tiles
    if (i < ROWS) out[i] = bv[0];
}

// ---------------- prep: split + tile/swizzle weights ------------------------
__global__ void prep_kernel(const float* __restrict__ W_ih, const float* __restrict__ W_hh) {
    int idx = blockIdx.x * blockDim.x + threadIdx.x;   // 786432
    if (idx >= G_DIM * H_DIM) return;
    int k = idx & 511, kt = k >> 6, c = k & 63;
    // W_ih -> [nt][kt] 128x64 tiles
    {
        int n = idx >> 9;
        int nt = n >> 7, m = n & 127;
        float v = W_ih[idx];
        __nv_bfloat16 hi = __float2bfloat16(v);
        __nv_bfloat16 lo = __float2bfloat16(v - __bfloat162float(hi));
        uint32_t off = SW128((uint32_t)(m * 128 + c * 2));
        *(__nv_bfloat16*)((char*)&g_WihT[0][nt][kt][0] + off) = hi;
        *(__nv_bfloat16*)((char*)&g_WihT[1][nt][kt][0] + off) = lo;
    }
    // W_hh gate-triple reorder -> [jc][kt] 96x64 tiles
    {
        int jtr = idx >> 9;
        int jc = jtr / 96, rem = jtr % 96;
        int gt = rem >> 5, jl = rem & 31;
        float v = W_hh[(size_t)(gt * 512 + jc * 32 + jl) * H_DIM + k];
        __nv_bfloat16 hi = __float2bfloat16(v);
        __nv_bfloat16 lo = __float2bfloat16(v - __bfloat162float(hi));
        uint32_t off = SW128((uint32_t)(rem * 128 + c * 2));
        *(__nv_bfloat16*)((char*)&g_WhhT[0][jc][kt][0] + off) = hi;
        *(__nv_bfloat16*)((char*)&g_WhhT[1][jc][kt][0] + off) = lo;
    }
}

// ---------------- gemm1: x = relu(obs @ W1^T + b1) -> swizzled tiles --------
__global__ __launch_bounds__(256, 2) void gemm1_kernel(
    const float* __restrict__ obs, const float* __restrict__ W1,
    const float* __restrict__ b1)
{
    __shared__ float As[16][132];
    __shared__ float Bs[16][132];
    const int tid = threadIdx.x;
    const int tx = tid & 15, ty = tid >> 4;
    const int row0 = blockIdx.y * 128;
    const int col0 = blockIdx.x * 128;

    float acc[8][8] = {};

    for (int k0 = 0; k0 < D_IN; k0 += 16) {
#pragma unroll
        for (int i = 0; i < 2; i++) {
            int idx = tid + i * 256;
            int row = idx >> 2;
            int kq  = (idx & 3) << 2;
            int r = row0 + row;
            int t = r >> 10;
            int n = r & 1023;
            size_t off = (size_t)(n >> 3) * 131072 + (size_t)t * 1024 + (size_t)(n & 7) * 128;
            float4 v = *(const float4*)(obs + off + k0 + kq);
            As[kq + 0][row] = v.x; As[kq + 1][row] = v.y;
            As[kq + 2][row] = v.z; As[kq + 3][row] = v.w;
        }
#pragma unroll
        for (int i = 0; i < 2; i++) {
            int idx = tid + i * 256;
            int row = idx >> 2;
            int kq  = (idx & 3) << 2;
            float4 v = *(const float4*)(W1 + (size_t)(col0 + row) * D_IN + k0 + kq);
            Bs[kq + 0][row] = v.x; Bs[kq + 1][row] = v.y;
            Bs[kq + 2][row] = v.z; Bs[kq + 3][row] = v.w;
        }
        __syncthreads();
#pragma unroll
        for (int k = 0; k < 16; k++) {
            float a[8], b[8];
            *(float4*)(a)     = *(const float4*)&As[k][ty * 8];
            *(float4*)(a + 4) = *(const float4*)&As[k][ty * 8 + 4];
            *(float4*)(b)     = *(const float4*)&Bs[k][tx * 8];
            *(float4*)(b + 4) = *(const float4*)&Bs[k][tx * 8 + 4];
#pragma unroll
            for (int i = 0; i < 8; i++)
#pragma unroll
                for (int j = 0; j < 8; j++)
                    acc[i][j] = fmaf(a[i], b[j], acc[i][j]);
        }
        __syncthreads();
    }

    const int rt = blockIdx.y;
#pragma unroll
    for (int i = 0; i < 8; i++) {
        int mloc = ty * 8 + i;
#pragma unroll
        for (int j = 0; j < 8; j += 2) {
            int col = col0 + tx * 8 + j;
            int kt = col >> 6, cc = col & 63;
            float v0 = fmaxf(acc[i][j + 0] + b1[col + 0], 0.0f);
            float v1 = fmaxf(acc[i][j + 1] + b1[col + 1], 0.0f);
            __nv_bfloat16 h0 = __float2bfloat16(v0);
            __nv_bfloat16 h1 = __float2bfloat16(v1);
            __nv_bfloat16 l0 = __float2bfloat16(v0 - __bfloat162float(h0));
            __nv_bfloat16 l1 = __float2bfloat16(v1 - __bfloat162float(h1));
            uint32_t ph = (uint32_t)__bfloat16_as_ushort(h0) | ((uint32_t)__bfloat16_as_ushort(h1) << 16);
            uint32_t pl = (uint32_t)__bfloat16_as_ushort(l0) | ((uint32_t)__bfloat16_as_ushort(l1) << 16);
            uint32_t off = SW128((uint32_t)(mloc * 128 + cc * 2));
            *(uint32_t*)((char*)&g_xT[0][rt][kt][0] + off) = ph;
            *(uint32_t*)((char*)&g_xT[1][rt][kt][0] + off) = pl;
        }
    }
}

// ---------------- gemm2: gi = x @ W_ih^T + b_ih  (bf16x3, bulk loads) -------
// CTA 128m x 128n, 8 warps (4m x 2n). 8 chunks of K=64, fused hi/lo passes.
// SMEM stage (64KB): Ahi@0 Alo@16K Bhi@32K Blo@48K; 2 stages from offset 1024.
__global__ __launch_bounds__(256, 1) void gemm2_kernel(const float* __restrict__ b_ih)
{
    extern __shared__ char smem[];
    const uint32_t sb = smem_u32(smem);
    const int tid = threadIdx.x;
    const int wid = tid >> 5, lane = tid & 31;
    const int mw = wid >> 1, nw = wid & 1;
    const int nt = blockIdx.x;
    const int rt = blockIdx.y;

    if (tid == 0) {
        MBAR_INIT(sb, 1);
        MBAR_INIT(sb + 8, 1);
        FENCE_ASYNC();
    }
    __syncthreads();

    float c[2][8][4] = {};

    auto issue = [&](int ch, int buf) {
        uint32_t mb = sb + buf * 8;
        uint32_t base = sb + 1024 + buf * 65536;
        MBAR_EXPECT(mb, 65536);
        BULK_G2S(base,         &g_xT[0][rt][ch][0],   16384, mb);
        BULK_G2S(base + 16384, &g_xT[1][rt][ch][0],   16384, mb);
        BULK_G2S(base + 32768, &g_WihT[0][nt][ch][0], 16384, mb);
        BULK_G2S(base + 49152, &g_WihT[1][nt][ch][0], 16384, mb);
    };

    if (tid == 0) { issue(0, 0); issue(1, 1); }

    for (int ch = 0; ch < 8; ch++) {
        const int buf = ch & 1;
        MBAR_WAIT_PARITY(sb + buf * 8, (ch >> 1) & 1);
        const uint32_t base = sb + 1024 + buf * 65536;
        const uint32_t sAh = base, sAl = base + 16384;
        const uint32_t sBh = base + 32768, sBl = base + 49152;

#pragma unroll
        for (int ks = 0; ks < 4; ks++) {
            uint32_t ah[2][4], al[2][4];
            uint32_t arow0 = mw * 32 + (lane & 15);
            uint32_t acol = ks * 16 + ((lane >> 4) << 3);
#pragma unroll
            for (int mi = 0; mi < 2; mi++) {
                uint32_t aoff = SW128((arow0 + mi * 16) * 128 + acol * 2);
                ldsm4(ah[mi], sAh + aoff);
                ldsm4(al[mi], sAl + aoff);
            }
#pragma unroll
            for (int bp = 0; bp < 4; bp++) {
                uint32_t b[4];
                uint32_t brow = nw * 64 + bp * 16 + (lane & 7) + ((lane >> 4) & 1) * 8;
                uint32_t bcol = ks * 16 + ((lane >> 3) & 1) * 8;
                ldsm4(b, sBh + SW128(brow * 128 + bcol * 2));
#pragma unroll
                for (int mi = 0; mi < 2; mi++) {
                    mma16816(c[mi][2 * bp],     ah[mi], b[0], b[1]);
                    mma16816(c[mi][2 * bp + 1], ah[mi], b[2], b[3]);
                    mma16816(c[mi][2 * bp],     al[mi], b[0], b[1]);
                    mma16816(c[mi][2 * bp + 1], al[mi], b[2], b[3]);
                }
            }
        }
        // pass 3: hi x B_lo
#pragma unroll
        for (int ks = 0; ks < 4; ks++) {
            uint32_t ah[2][4];
            uint32_t arow0 = mw * 32 + (lane & 15);
            uint32_t acol = ks * 16 + ((lane >> 4) << 3);
#pragma unroll
            for (int mi = 0; mi < 2; mi++)
                ldsm4(ah[mi], sAh + SW128((arow0 + mi * 16) * 128 + acol * 2));
#pragma unroll
            for (int bp = 0; bp < 4; bp++) {
                uint32_t b[4];
                uint32_t brow = nw * 64 + bp * 16 + (lane & 7) + ((lane >> 4) & 1) * 8;
                uint32_t bcol = ks * 16 + ((lane >> 3) & 1) * 8;
                ldsm4(b, sBl + SW128(brow * 128 + bcol * 2));
#pragma unroll
                for (int mi = 0; mi < 2; mi++) {
                    mma16816(c[mi][2 * bp],     ah[mi], b[0], b[1]);
                    mma16816(c[mi][2 * bp + 1], ah[mi], b[2], b[3]);
                }
            }
        }
        __syncthreads();
        if (tid == 0 && ch + 2 < 8) issue(ch + 2, buf);
    }

    // epilogue
    const int r0 = rt * 128, n0 = nt * 128;
    const int g = lane >> 2, ct = lane & 3;
#pragma unroll
    for (int mi = 0; mi < 2; mi++) {
#pragma unroll
        for (int ntl = 0; ntl < 8; ntl++) {
            int m = r0 + mw * 32 + mi * 16 + g;
            int n = n0 + nw * 64 + ntl * 8 + ct * 2;
            float2 bi = *(const float2*)(b_ih + n);
            float2 v0, v1;
            v0.x = c[mi][ntl][0] + bi.x; v0.y = c[mi][ntl][1] + bi.y;
            v1.x = c[mi][ntl][2] + bi.x; v1.y = c[mi][ntl][3] + bi.y;
            *(float2*)(g_gi + (size_t)m * G_DIM + n)       = v0;
            *(float2*)(g_gi + (size_t)(m + 8) * G_DIM + n) = v1;
        }
    }
}

// ---------------- gru step: gh = h @ W_hh^T + fused epilogue ----------------
// grid (16 jc, 8 mt). CTA: 128m x 96 gate-triple rows. 8 chunks, fused passes.
// SMEM stage (56KB): Ahi@0 Alo@16K Bhi@32K Blo@44K; 2 stages from 1024.
__global__ __launch_bounds__(256, 1) void gru_step_kernel(
    const float* __restrict__ b_hh, const float* __restrict__ Wv,
    float* __restrict__ out, int t)
{
    extern __shared__ char smem[];
    const uint32_t sb = smem_u32(smem);
    const int tid = threadIdx.x;
    const int wid = tid >> 5, lane = tid & 31;
    const int jc = blockIdx.x;    // 0..15
    const int mt = blockIdx.y;    // 0..7
    const int rd = t & 1, wr = (t + 1) & 1;

    if (tid == 0) {
        MBAR_INIT(sb, 1);
        MBAR_INIT(sb + 8, 1);
        FENCE_ASYNC();
    }
    __syncthreads();

    float c[12][4] = {};

    auto issue = [&](int ch, int buf) {
        uint32_t mb = sb + buf * 8;
        uint32_t base = sb + 1024 + buf * 57344;
        MBAR_EXPECT(mb, 57344);
        BULK_G2S(base,         &g_AT[rd][0][mt][ch][0], 16384, mb);
        BULK_G2S(base + 16384, &g_AT[rd][1][mt][ch][0], 16384, mb);
        BULK_G2S(base + 32768, &g_WhhT[0][jc][ch][0],   12288, mb);
        BULK_G2S(base + 45056, &g_WhhT[1][jc][ch][0],   12288, mb);
    };

    if (tid == 0) { issue(0, 0); issue(1, 1); }

    for (int ch = 0; ch < 8; ch++) {
        const int buf = ch & 1;
        MBAR_WAIT_PARITY(sb + buf * 8, (ch >> 1) & 1);
        const uint32_t base = sb + 1024 + buf * 57344;
        const uint32_t sAh = base, sAl = base + 16384;
        const uint32_t sBh = base + 32768, sBl = base + 45056;

#pragma unroll
        for (int ks = 0; ks < 4; ks++) {
            uint32_t ah[4], al[4];
            uint32_t arow = wid * 16 + (lane & 15);
            uint32_t acol = ks * 16 + ((lane >> 4) << 3);
            uint32_t aoff = SW128(arow * 128 + acol * 2);
            ldsm4(ah, sAh + aoff);
            ldsm4(al, sAl + aoff);
#pragma unroll
            for (int bt = 0; bt < 6; bt++) {
                uint32_t b[4];
                uint32_t brow = bt * 16 + (lane & 7) + ((lane >> 4) & 1) * 8;
                uint32_t bcol = ks * 16 + ((lane >> 3) & 1) * 8;
                ldsm4(b, sBh + SW128(brow * 128 + bcol * 2));
                mma16816(c[2 * bt],     ah, b[0], b[1]);
                mma16816(c[2 * bt + 1], ah, b[2], b[3]);
                mma16816(c[2 * bt],     al, b[0], b[1]);
                mma16816(c[2 * bt + 1], al, b[2], b[3]);
            }
        }
#pragma unroll
        for (int ks = 0; ks < 4; ks++) {
            uint32_t ah[4];
            uint32_t arow = wid * 16 + (lane & 15);
            uint32_t acol = ks * 16 + ((lane >> 4) << 3);
            ldsm4(ah, sAh + SW128(arow * 128 + acol * 2));
#pragma unroll
            for (int bt = 0; bt < 6; bt++) {
                uint32_t b[4];
                uint32_t brow = bt * 16 + (lane & 7) + ((lane >> 4) & 1) * 8;
                uint32_t bcol = ks * 16 + ((lane >> 3) & 1) * 8;
                ldsm4(b, sBl + SW128(brow * 128 + bcol * 2));
                mma16816(c[2 * bt],     ah, b[0], b[1]);
                mma16816(c[2 * bt + 1], ah, b[2], b[3]);
            }
        }
        __syncthreads();
        if (tid == 0 && ch + 2 < 8) issue(ch + 2, buf);
    }

    // ---------------- fused epilogue ----------------
    const int g = lane >> 2, ct = lane & 3;
    const int j_base = jc * 32;

#pragma unroll
    for (int mi = 0; mi < 2; mi++) {
        int mloc = wid * 16 + g + mi * 8;
        int m_g = mt * 128 + mloc;
        const float* gi_row = g_gi + ((size_t)t * NB + m_g) * G_DIM + j_base;
        const float* hp_row = g_hf[rd] + (size_t)m_g * H_DIM + j_base;
        float*       hn_row = g_hf[wr] + (size_t)m_g * H_DIM + j_base;

        float vp = 0.0f;
#pragma unroll
        for (int jj = 0; jj < 4; jj++) {
            int jl = jj * 8 + ct * 2;
            int j  = j_base + jl;
            float2 gr = *(const float2*)(gi_row + jl);
            float2 gz = *(const float2*)(gi_row + 512 + jl);
            float2 gn = *(const float2*)(gi_row + 1024 + jl);
            float2 br = *(const float2*)(b_hh + j);
            float2 bz = *(const float2*)(b_hh + 512 + j);
            float2 bn = *(const float2*)(b_hh + 1024 + j);
            float2 hp = *(const float2*)(hp_row + jl);
            float2 wv = *(const float2*)(Wv + j);

            float r0 = sigf(gr.x + br.x + c[jj][mi * 2]);
            float r1 = sigf(gr.y + br.y + c[jj][mi * 2 + 1]);
            float z0 = sigf(gz.x + bz.x + c[4 + jj][mi * 2]);
            float z1 = sigf(gz.y + bz.y + c[4 + jj][mi * 2 + 1]);
            float nt0 = tanhf(gn.x + r0 * (c[8 + jj][mi * 2] + bn.x));
            float nt1 = tanhf(gn.y + r1 * (c[8 + jj][mi * 2 + 1] + bn.y));
            float h0 = (1.0f - z0) * nt0 + z0 * hp.x;
            float h1 = (1.0f - z1) * nt1 + z1 * hp.y;

            float2 hw; hw.x = h0; hw.y = h1;
            *(float2*)(hn_row + jl) = hw;

            __nv_bfloat16 hh0 = __float2bfloat16(h0);
            __nv_bfloat16 hh1 = __float2bfloat16(h1);
            __nv_bfloat16 ll0 = __float2bfloat16(h0 - __bfloat162float(hh0));
            __nv_bfloat16 ll1 = __float2bfloat16(h1 - __bfloat162float(hh1));
            uint32_t ph = (uint32_t)__bfloat16_as_ushort(hh0) | ((uint32_t)__bfloat16_as_ushort(hh1) << 16);
            uint32_t pl = (uint32_t)__bfloat16_as_ushort(ll0) | ((uint32_t)__bfloat16_as_ushort(ll1) << 16);
            int kt = j >> 6, cc = j & 63;
            uint32_t off = SW128((uint32_t)(mloc * 128 + cc * 2));
            *(uint32_t*)((char*)&g_AT[wr][0][mt][kt][0] + off) = ph;
            *(uint32_t*)((char*)&g_AT[wr][1][mt][kt][0] + off) = pl;

            vp = fmaf(wv.x, h0, vp);
            vp = fmaf(wv.y, h1, vp);
        }
        vp += __shfl_xor_sync(0xffffffffu, vp, 1);
        vp += __shfl_xor_sync(0xffffffffu, vp, 2);
        if (ct == 0) {
            int bs = m_g >> 3, a = m_g & 7;
            atomicAdd(&out[((size_t)bs * T_LEN + t) * 8 + a], vp);
        }
    }
}

// ---------------------------------------------------------------------------
extern "C" void kernel_launch(void* const* d_in, const int* in_sizes, int n_in,
                              void* d_out, int out_size)
{
    const float* obs  = (const float*)d_in[0];
    const float* W1   = (const float*)d_in[1];
    const float* b1   = (const float*)d_in[2];
    const float* W_ih = (const float*)d_in[3];
    const float* b_ih = (const float*)d_in[4];
    const float* W_hh = (const float*)d_in[5];
    const float* b_hh = (const float*)d_in[6];
    const float* Wv   = (const float*)d_in[7];
    const float* bv   = (const float*)d_in[8];
    float* out = (float*)d_out;

    cudaFuncSetAttribute(gemm2_kernel,    cudaFuncAttributeMaxDynamicSharedMemorySize, 132096);
    cudaFuncSetAttribute(gru_step_kernel, cudaFuncAttributeMaxDynamicSharedMemorySize, 115712);

    init_kernel<<<2048, 256>>>(out, bv);
    prep_kernel<<<3072, 256>>>(W_ih, W_hh);
    gemm1_kernel<<<dim3(4, 1024), 256>>>(obs, W1, b1);
    gemm2_kernel<<<dim3(12, 1024), 256, 132096>>>(b_ih);
    for (int t = 0; t < T_LEN; t++)
        gru_step_kernel<<<dim3(16, 8), 256, 115712>>>(b_hh, Wv, out, t);
}

// round 5
// speedup vs baseline: 4.2678x; 1.3023x over previous
#include <cuda_runtime.h>
#include <cuda_fp16.h>
#include <math.h>
#include <stdint.h>

#define T_LEN 128
#define NB    1024
#define D_IN  128
#define H_DIM 512
#define G_DIM 1536
#define ROWS  (T_LEN * NB)     // 131072

// ---------------- scratch (__device__ globals) ------------------------------
__device__ __half g_xT[1024][8][8192];      // x fp16 tiles [rt][kt] 128x64, SW128
__device__ __half g_WihT[2][12][8][8192];   // W_ih hi/lo tiles [nt][kt] 128x64
__device__ __half g_WhhT[2][16][8][6144];   // W_hh hi/lo tiles [jc][kt] 96x64 (gate-triple)
__device__ __half g_hT[2][8][8][8192];      // h fp16 tiles ping-pong [mt][kt] 128x64
__device__ float  g_gi[(size_t)ROWS * G_DIM];
__device__ unsigned g_cnt, g_gen;           // software grid barrier state

__device__ __forceinline__ float sigf(float x) { return 1.0f / (1.0f + expf(-x)); }

#define SW128(off) ((off) ^ (((off) >> 3) & 0x70))

__device__ __forceinline__ uint32_t smem_u32(const void* p) {
    uint32_t a;
    asm("{ .reg .u64 t; cvta.to.shared.u64 t, %1; cvt.u32.u64 %0, t; }" : "=r"(a) : "l"(p));
    return a;
}

#define MBAR_INIT(addr, cnt) \
    asm volatile("mbarrier.init.shared.b64 [%0], %1;" :: "r"(addr), "r"(cnt) : "memory")
#define MBAR_EXPECT(addr, bytes) \
    asm volatile("mbarrier.arrive.expect_tx.shared.b64 _, [%0], %1;" :: "r"(addr), "r"(bytes) : "memory")
#define FENCE_ASYNC() asm volatile("fence.proxy.async.shared::cta;" ::: "memory")

#define MBAR_WAIT_PARITY(addr, par) do {                                        \
    uint32_t _m = (addr); uint32_t _p = (par); uint32_t _d;                     \
    asm volatile("{\n\t.reg .pred p;\n\t"                                       \
        "mbarrier.try_wait.parity.acquire.cta.shared::cta.b64 p, [%1], %2;\n\t" \
        "selp.b32 %0, 1, 0, p;\n\t}" : "=r"(_d) : "r"(_m), "r"(_p) : "memory"); \
    if (!_d) {                                                                  \
        asm volatile("{\n\t.reg .pred P1;\n\t"                                  \
        "WL_%=:\n\t"                                                            \
        "mbarrier.try_wait.parity.acquire.cta.shared::cta.b64 P1, [%0], %1, 0x989680;\n\t" \
        "@P1 bra.uni WD_%=;\n\t"                                                \
        "bra.uni WL_%=;\n\t"                                                    \
        "WD_%=:\n\t}" :: "r"(_m), "r"(_p) : "memory");                          \
    }                                                                           \
} while (0)

#define BULK_G2S(dst, src, bytes, mbar) \
    asm volatile("cp.async.bulk.shared::cta.global.mbarrier::complete_tx::bytes [%0], [%1], %2, [%3];" \
        :: "r"(dst), "l"(src), "r"((uint32_t)(bytes)), "r"(mbar) : "memory")

#define PREFETCH_L2(p) asm volatile("prefetch.global.L2 [%0];" :: "l"(p))

__device__ __forceinline__ void ldsm4(uint32_t (&r)[4], uint32_t addr) {
    asm volatile("ldmatrix.sync.aligned.m8n8.x4.shared.b16 {%0,%1,%2,%3}, [%4];"
        : "=r"(r[0]), "=r"(r[1]), "=r"(r[2]), "=r"(r[3]) : "r"(addr));
}
__device__ __forceinline__ void mma16816(float (&c)[4], const uint32_t (&a)[4],
                                         uint32_t b0, uint32_t b1) {
    asm volatile(
        "mma.sync.aligned.m16n8k16.row.col.f32.f16.f16.f32 "
        "{%0,%1,%2,%3}, {%4,%5,%6,%7}, {%8,%9}, {%0,%1,%2,%3};"
        : "+f"(c[0]), "+f"(c[1]), "+f"(c[2]), "+f"(c[3])
        : "r"(a[0]), "r"(a[1]), "r"(a[2]), "r"(a[3]), "r"(b0), "r"(b1));
}

// ---------------- init ------------------------------------------------------
__global__ void init_kernel(float* __restrict__ out, const float* __restrict__ bv) {
    int i = blockIdx.x * blockDim.x + threadIdx.x;   // 524288 threads
    if (i < 262144) ((uint32_t*)&g_hT[0][0][0][0])[i] = 0u;   // zero h0 tiles
    if (i < ROWS) out[i] = bv[0];
    if (i == 0) { g_cnt = 0u; g_gen = 0u; }
}

// ---------------- prep: split + tile/swizzle weights (fp16 hi/lo) -----------
__global__ void prep_kernel(const float* __restrict__ W_ih, const float* __restrict__ W_hh) {
    int idx = blockIdx.x * blockDim.x + threadIdx.x;   // 786432
    if (idx >= G_DIM * H_DIM) return;
    int k = idx & 511, kt = k >> 6, c = k & 63;
    // W_ih -> [nt][kt] 128x64 tiles, hi/lo
    {
        int n = idx >> 9;
        int nt = n >> 7, m = n & 127;
        float v = W_ih[idx];
        __half hi = __float2half_rn(v);
        __half lo = __float2half_rn(v - __half2float(hi));
        uint32_t off = SW128((uint32_t)(m * 128 + c * 2));
        *(__half*)((char*)&g_WihT[0][nt][kt][0] + off) = hi;
        *(__half*)((char*)&g_WihT[1][nt][kt][0] + off) = lo;
    }
    // W_hh gate-triple reorder -> [jc][kt] 96x64 tiles, hi/lo
    {
        int jtr = idx >> 9;
        int jc = jtr / 96, rem = jtr % 96;
        int gt = rem >> 5, jl = rem & 31;
        float v = W_hh[(size_t)(gt * 512 + jc * 32 + jl) * H_DIM + k];
        __half hi = __float2half_rn(v);
        __half lo = __float2half_rn(v - __half2float(hi));
        uint32_t off = SW128((uint32_t)(rem * 128 + c * 2));
        *(__half*)((char*)&g_WhhT[0][jc][kt][0] + off) = hi;
        *(__half*)((char*)&g_WhhT[1][jc][kt][0] + off) = lo;
    }
}

// ---------------- gemm1: x = relu(obs @ W1^T + b1) -> fp16 tiles ------------
__global__ __launch_bounds__(256, 2) void gemm1_kernel(
    const float* __restrict__ obs, const float* __restrict__ W1,
    const float* __restrict__ b1)
{
    __shared__ float As[16][132];
    __shared__ float Bs[16][132];
    const int tid = threadIdx.x;
    const int tx = tid & 15, ty = tid >> 4;
    const int row0 = blockIdx.y * 128;
    const int col0 = blockIdx.x * 128;

    float acc[8][8] = {};

    for (int k0 = 0; k0 < D_IN; k0 += 16) {
#pragma unroll
        for (int i = 0; i < 2; i++) {
            int idx = tid + i * 256;
            int row = idx >> 2;
            int kq  = (idx & 3) << 2;
            int r = row0 + row;
            int t = r >> 10;
            int n = r & 1023;
            size_t off = (size_t)(n >> 3) * 131072 + (size_t)t * 1024 + (size_t)(n & 7) * 128;
            float4 v = *(const float4*)(obs + off + k0 + kq);
            As[kq + 0][row] = v.x; As[kq + 1][row] = v.y;
            As[kq + 2][row] = v.z; As[kq + 3][row] = v.w;
        }
#pragma unroll
        for (int i = 0; i < 2; i++) {
            int idx = tid + i * 256;
            int row = idx >> 2;
            int kq  = (idx & 3) << 2;
            float4 v = *(const float4*)(W1 + (size_t)(col0 + row) * D_IN + k0 + kq);
            Bs[kq + 0][row] = v.x; Bs[kq + 1][row] = v.y;
            Bs[kq + 2][row] = v.z; Bs[kq + 3][row] = v.w;
        }
        __syncthreads();
#pragma unroll
        for (int k = 0; k < 16; k++) {
            float a[8], b[8];
            *(float4*)(a)     = *(const float4*)&As[k][ty * 8];
            *(float4*)(a + 4) = *(const float4*)&As[k][ty * 8 + 4];
            *(float4*)(b)     = *(const float4*)&Bs[k][tx * 8];
            *(float4*)(b + 4) = *(const float4*)&Bs[k][tx * 8 + 4];
#pragma unroll
            for (int i = 0; i < 8; i++)
#pragma unroll
                for (int j = 0; j < 8; j++)
                    acc[i][j] = fmaf(a[i], b[j], acc[i][j]);
        }
        __syncthreads();
    }

    const int rt = blockIdx.y;
#pragma unroll
    for (int i = 0; i < 8; i++) {
        int mloc = ty * 8 + i;
#pragma unroll
        for (int j = 0; j < 8; j += 2) {
            int col = col0 + tx * 8 + j;
            int kt = col >> 6, cc = col & 63;
            float v0 = fmaxf(acc[i][j + 0] + b1[col + 0], 0.0f);
            float v1 = fmaxf(acc[i][j + 1] + b1[col + 1], 0.0f);
            __half h0 = __float2half_rn(v0);
            __half h1 = __float2half_rn(v1);
            uint32_t ph = (uint32_t)__half_as_ushort(h0) | ((uint32_t)__half_as_ushort(h1) << 16);
            uint32_t off = SW128((uint32_t)(mloc * 128 + cc * 2));
            *(uint32_t*)((char*)&g_xT[rt][kt][0] + off) = ph;
        }
    }
}

// ---------------- gemm2: gi = x @ W_ih^T + b_ih  (fp16x2, bulk loads) -------
// CTA 128m x 128n, 8 warps (4m x 2n). 8 chunks of K=64, 2 fused passes.
// SMEM stage (48KB): A@0, Wh@16K, Wl@32K; 2 stages from offset 1024. = 99328 B
__global__ __launch_bounds__(256, 2) void gemm2_kernel(const float* __restrict__ b_ih)
{
    extern __shared__ char smem[];
    const uint32_t sb = smem_u32(smem);
    const int tid = threadIdx.x;
    const int wid = tid >> 5, lane = tid & 31;
    const int mw = wid >> 1, nw = wid & 1;
    const int nt = blockIdx.x;
    const int rt = blockIdx.y;

    if (tid == 0) {
        MBAR_INIT(sb, 1);
        MBAR_INIT(sb + 8, 1);
        FENCE_ASYNC();
    }
    __syncthreads();

    float c[2][8][4] = {};

    auto issue = [&](int ch, int buf) {
        uint32_t mb = sb + buf * 8;
        uint32_t base = sb + 1024 + buf * 49152;
        MBAR_EXPECT(mb, 49152);
        BULK_G2S(base,         &g_xT[rt][ch][0],      16384, mb);
        BULK_G2S(base + 16384, &g_WihT[0][nt][ch][0], 16384, mb);
        BULK_G2S(base + 32768, &g_WihT[1][nt][ch][0], 16384, mb);
    };

    if (tid == 0) { issue(0, 0); issue(1, 1); }

    for (int ch = 0; ch < 8; ch++) {
        const int buf = ch & 1;
        MBAR_WAIT_PARITY(sb + buf * 8, (ch >> 1) & 1);
        const uint32_t base = sb + 1024 + buf * 49152;
        const uint32_t sA = base, sBh = base + 16384, sBl = base + 32768;

#pragma unroll
        for (int ks = 0; ks < 4; ks++) {
            uint32_t a[2][4];
            uint32_t arow0 = mw * 32 + (lane & 15);
            uint32_t acol = ks * 16 + ((lane >> 4) << 3);
#pragma unroll
            for (int mi = 0; mi < 2; mi++)
                ldsm4(a[mi], sA + SW128((arow0 + mi * 16) * 128 + acol * 2));
#pragma unroll
            for (int bp = 0; bp < 4; bp++) {
                uint32_t bh[4], bl[4];
                uint32_t brow = nw * 64 + bp * 16 + (lane & 7) + ((lane >> 4) & 1) * 8;
                uint32_t bcol = ks * 16 + ((lane >> 3) & 1) * 8;
                uint32_t boff = SW128(brow * 128 + bcol * 2);
                ldsm4(bh, sBh + boff);
                ldsm4(bl, sBl + boff);
#pragma unroll
                for (int mi = 0; mi < 2; mi++) {
                    mma16816(c[mi][2 * bp],     a[mi], bh[0], bh[1]);
                    mma16816(c[mi][2 * bp + 1], a[mi], bh[2], bh[3]);
                    mma16816(c[mi][2 * bp],     a[mi], bl[0], bl[1]);
                    mma16816(c[mi][2 * bp + 1], a[mi], bl[2], bl[3]);
                }
            }
        }
        __syncthreads();
        if (tid == 0 && ch + 2 < 8) issue(ch + 2, buf);
    }

    // epilogue
    const int r0 = rt * 128, n0 = nt * 128;
    const int g = lane >> 2, ct = lane & 3;
#pragma unroll
    for (int mi = 0; mi < 2; mi++) {
#pragma unroll
        for (int ntl = 0; ntl < 8; ntl++) {
            int m = r0 + mw * 32 + mi * 16 + g;
            int n = n0 + nw * 64 + ntl * 8 + ct * 2;
            float2 bi = *(const float2*)(b_ih + n);
            float2 v0, v1;
            v0.x = c[mi][ntl][0] + bi.x; v0.y = c[mi][ntl][1] + bi.y;
            v1.x = c[mi][ntl][2] + bi.x; v1.y = c[mi][ntl][3] + bi.y;
            *(float2*)(g_gi + (size_t)m * G_DIM + n)       = v0;
            *(float2*)(g_gi + (size_t)(m + 8) * G_DIM + n) = v1;
        }
    }
}

// ---------------- persistent GRU scan ---------------------------------------
// grid (16 jc, 8 mt) = 128 CTAs, all resident (1/SM). W_hh jc-slice persistent
// in SMEM (192KB); h_prev in registers; h fp16 tiles ping-pong via global;
// software grid barrier between steps.
// SMEM: mbars@0..24, A stage0 @1024 (16KB), stage1 @17408, W @33792 (8x24KB).
// total = 230400 bytes.
__global__ __launch_bounds__(256, 1) void gru_persist_kernel(
    const float* __restrict__ b_hh, const float* __restrict__ Wv,
    const float* __restrict__ gi_base_dummy, float* __restrict__ out)
{
    extern __shared__ char smem[];
    const uint32_t sb = smem_u32(smem);
    const int tid = threadIdx.x;
    const int wid = tid >> 5, lane = tid & 31;
    const int jc = blockIdx.x;    // 0..15
    const int mt = blockIdx.y;    // 0..7

    const uint32_t mbA0 = sb, mbA1 = sb + 8, mbW = sb + 16;
    const uint32_t A0 = sb + 1024, A1 = sb + 17408, W0 = sb + 33792;

    if (tid == 0) {
        MBAR_INIT(mbA0, 1);
        MBAR_INIT(mbA1, 1);
        MBAR_INIT(mbW, 1);
        FENCE_ASYNC();
    }
    __syncthreads();

    if (tid == 0) {
        MBAR_EXPECT(mbW, 196608);
#pragma unroll
        for (int ch = 0; ch < 8; ch++) {
            BULK_G2S(W0 + ch * 24576,         &g_WhhT[0][jc][ch][0], 12288, mbW);
            BULK_G2S(W0 + ch * 24576 + 12288, &g_WhhT[1][jc][ch][0], 12288, mbW);
        }
    }

    // per-thread constants
    const int g = lane >> 2, ct = lane & 3;
    const int jbase = jc * 32;
    float2 brv[4], bzv[4], bnv[4], wvv[4];
#pragma unroll
    for (int jj = 0; jj < 4; jj++) {
        int j = jbase + jj * 8 + ct * 2;
        brv[jj] = *(const float2*)(b_hh + j);
        bzv[jj] = *(const float2*)(b_hh + 512 + j);
        bnv[jj] = *(const float2*)(b_hh + 1024 + j);
        wvv[jj] = *(const float2*)(Wv + j);
    }
    float hreg[2][4][2];
#pragma unroll
    for (int mi = 0; mi < 2; mi++)
#pragma unroll
        for (int jj = 0; jj < 4; jj++)
            hreg[mi][jj][0] = hreg[mi][jj][1] = 0.0f;

    MBAR_WAIT_PARITY(mbW, 0);

    int pA0 = 0, pA1 = 0;

    for (int t = 0; t < T_LEN; t++) {
        const int rd = t & 1, wr = (t + 1) & 1;
        if (tid == 0) {
            MBAR_EXPECT(mbA0, 16384);
            BULK_G2S(A0, &g_hT[rd][mt][0][0], 16384, mbA0);
            MBAR_EXPECT(mbA1, 16384);
            BULK_G2S(A1, &g_hT[rd][mt][1][0], 16384, mbA1);
        }
        // L2 prefetch of this step's gi slice
        const float* gi_t = g_gi + ((size_t)t * NB + mt * 128) * G_DIM;
        for (int i = tid; i < 512; i += 256) {
            int r = i >> 2, gg = i & 3;
            if (gg < 3) PREFETCH_L2(gi_t + (size_t)r * G_DIM + gg * 512 + jbase);
        }

        float c[12][4] = {};

        for (int ch = 0; ch < 8; ch++) {
            const uint32_t mb = (ch & 1) ? mbA1 : mbA0;
            const uint32_t Ab = (ch & 1) ? A1 : A0;
            if (ch & 1) { MBAR_WAIT_PARITY(mb, pA1); pA1 ^= 1; }
            else        { MBAR_WAIT_PARITY(mb, pA0); pA0 ^= 1; }
            const uint32_t Wc = W0 + ch * 24576;
#pragma unroll
            for (int ks = 0; ks < 4; ks++) {
                uint32_t a[4];
                uint32_t arow = wid * 16 + (lane & 15);
                uint32_t acol = ks * 16 + ((lane >> 4) << 3);
                ldsm4(a, Ab + SW128(arow * 128 + acol * 2));
#pragma unroll
                for (int bt = 0; bt < 6; bt++) {
                    uint32_t bh[4], bl[4];
                    uint32_t brow = bt * 16 + (lane & 7) + ((lane >> 4) & 1) * 8;
                    uint32_t bcol = ks * 16 + ((lane >> 3) & 1) * 8;
                    uint32_t boff = SW128(brow * 128 + bcol * 2);
                    ldsm4(bh, Wc + boff);
                    ldsm4(bl, Wc + 12288 + boff);
                    mma16816(c[2 * bt],     a, bh[0], bh[1]);
                    mma16816(c[2 * bt + 1], a, bh[2], bh[3]);
                    mma16816(c[2 * bt],     a, bl[0], bl[1]);
                    mma16816(c[2 * bt + 1], a, bl[2], bl[3]);
                }
            }
            __syncthreads();
            if (tid == 0 && ch + 2 < 8) {
                MBAR_EXPECT(mb, 16384);
                BULK_G2S(Ab, &g_hT[rd][mt][ch + 2][0], 16384, mb);
            }
        }

        // ---------------- fused epilogue ----------------
#pragma unroll
        for (int mi = 0; mi < 2; mi++) {
            int mloc = wid * 16 + g + mi * 8;
            int m_g = mt * 128 + mloc;
            const float* gi_row = gi_t + (size_t)mloc * G_DIM;

            float vp = 0.0f;
#pragma unroll
            for (int jj = 0; jj < 4; jj++) {
                int jl = jj * 8 + ct * 2;
                int j  = jbase + jl;
                float2 gr = *(const float2*)(gi_row + j);
                float2 gz = *(const float2*)(gi_row + 512 + j);
                float2 gn = *(const float2*)(gi_row + 1024 + j);

                float r0 = sigf(gr.x + brv[jj].x + c[jj][mi * 2]);
                float r1 = sigf(gr.y + brv[jj].y + c[jj][mi * 2 + 1]);
                float z0 = sigf(gz.x + bzv[jj].x + c[4 + jj][mi * 2]);
                float z1 = sigf(gz.y + bzv[jj].y + c[4 + jj][mi * 2 + 1]);
                float nt0 = tanhf(gn.x + r0 * (c[8 + jj][mi * 2] + bnv[jj].x));
                float nt1 = tanhf(gn.y + r1 * (c[8 + jj][mi * 2 + 1] + bnv[jj].y));
                float h0 = (1.0f - z0) * nt0 + z0 * hreg[mi][jj][0];
                float h1 = (1.0f - z1) * nt1 + z1 * hreg[mi][jj][1];
                hreg[mi][jj][0] = h0;
                hreg[mi][jj][1] = h1;

                __half hh0 = __float2half_rn(h0);
                __half hh1 = __float2half_rn(h1);
                uint32_t ph = (uint32_t)__half_as_ushort(hh0) | ((uint32_t)__half_as_ushort(hh1) << 16);
                int kt = j >> 6, cc = j & 63;
                uint32_t off = SW128((uint32_t)(mloc * 128 + cc * 2));
                *(uint32_t*)((char*)&g_hT[wr][mt][kt][0] + off) = ph;

                vp = fmaf(wvv[jj].x, h0, vp);
                vp = fmaf(wvv[jj].y, h1, vp);
            }
            vp += __shfl_xor_sync(0xffffffffu, vp, 1);
            vp += __shfl_xor_sync(0xffffffffu, vp, 2);
            if (ct == 0) {
                int bs = m_g >> 3, a = m_g & 7;
                atomicAdd(&out[((size_t)bs * T_LEN + t) * 8 + a], vp);
            }
        }

        __syncthreads();
        // ---------------- software grid barrier ----------------
        if (t < T_LEN - 1) {
            if (tid == 0) {
                __threadfence();
                unsigned arr = atomicAdd(&g_cnt, 1u);
                if (arr == 127u) {
                    g_cnt = 0u;
                    __threadfence();
                    atomicExch(&g_gen, (unsigned)(t + 1));
                } else {
                    while (*(volatile unsigned*)&g_gen <= (unsigned)t) { }
                    __threadfence();
                }
            }
            __syncthreads();
        }
    }
}

// ---------------------------------------------------------------------------
extern "C" void kernel_launch(void* const* d_in, const int* in_sizes, int n_in,
                              void* d_out, int out_size)
{
    const float* obs  = (const float*)d_in[0];
    const float* W1   = (const float*)d_in[1];
    const float* b1   = (const float*)d_in[2];
    const float* W_ih = (const float*)d_in[3];
    const float* b_ih = (const float*)d_in[4];
    const float* W_hh = (const float*)d_in[5];
    const float* b_hh = (const float*)d_in[6];
    const float* Wv   = (const float*)d_in[7];
    const float* bv   = (const float*)d_in[8];
    float* out = (float*)d_out;

    cudaFuncSetAttribute(gemm2_kernel,       cudaFuncAttributeMaxDynamicSharedMemorySize, 99328);
    cudaFuncSetAttribute(gru_persist_kernel, cudaFuncAttributeMaxDynamicSharedMemorySize, 230400);

    init_kernel<<<2048, 256>>>(out, bv);
    prep_kernel<<<3072, 256>>>(W_ih, W_hh);
    gemm1_kernel<<<dim3(4, 1024), 256>>>(obs, W1, b1);
    gemm2_kernel<<<dim3(12, 1024), 256, 99328>>>(b_ih);
    gru_persist_kernel<<<dim3(16, 8), 256, 230400>>>(b_hh, Wv, nullptr, out);
}

// round 6
// speedup vs baseline: 5.2383x; 1.2274x over previous
#include <cuda_runtime.h>
#include <cuda_fp16.h>
#include <math.h>
#include <stdint.h>

#define T_LEN 128
#define NB    1024
#define D_IN  128
#define H_DIM 512
#define G_DIM 1536
#define ROWS  (T_LEN * NB)     // 131072

// ---------------- scratch (__device__ globals) ------------------------------
__device__ __half g_oT[1024][2][8192];      // obs fp16 tiles [rt][kt] 128x64, SW128
__device__ __half g_W1T[2][4][2][8192];     // W1 hi/lo tiles [nt][kt] 128x64
__device__ __half g_xT[1024][8][8192];      // x fp16 tiles [rt][kt] 128x64, SW128
__device__ __half g_WihT[2][12][8][8192];   // W_ih hi/lo tiles [nt][kt] 128x64
__device__ __half g_WhhT[2][16][8][6144];   // W_hh hi/lo tiles [jc][kt] 96x64 (gate-triple)
__device__ __half g_hT[2][8][8][8192];      // h fp16 tiles ping-pong [mt][kt] 128x64
__device__ float  g_gi[(size_t)ROWS * G_DIM];
__device__ unsigned g_arr[T_LEN];           // per-step grid-barrier arrive counters

__device__ __forceinline__ float sigf(float x) {
    return __fdividef(1.0f, 1.0f + __expf(-x));
}
__device__ __forceinline__ float tanhfast(float x) {
    return 2.0f * sigf(2.0f * x) - 1.0f;
}

#define SW128(off) ((off) ^ (((off) >> 3) & 0x70))

__device__ __forceinline__ uint32_t smem_u32(const void* p) {
    uint32_t a;
    asm("{ .reg .u64 t; cvta.to.shared.u64 t, %1; cvt.u32.u64 %0, t; }" : "=r"(a) : "l"(p));
    return a;
}

#define MBAR_INIT(addr, cnt) \
    asm volatile("mbarrier.init.shared.b64 [%0], %1;" :: "r"(addr), "r"(cnt) : "memory")
#define MBAR_EXPECT(addr, bytes) \
    asm volatile("mbarrier.arrive.expect_tx.shared.b64 _, [%0], %1;" :: "r"(addr), "r"(bytes) : "memory")
#define FENCE_ASYNC() asm volatile("fence.proxy.async.shared::cta;" ::: "memory")

#define MBAR_WAIT_PARITY(addr, par) do {                                        \
    uint32_t _m = (addr); uint32_t _p = (par); uint32_t _d;                     \
    asm volatile("{\n\t.reg .pred p;\n\t"                                       \
        "mbarrier.try_wait.parity.acquire.cta.shared::cta.b64 p, [%1], %2;\n\t" \
        "selp.b32 %0, 1, 0, p;\n\t}" : "=r"(_d) : "r"(_m), "r"(_p) : "memory"); \
    if (!_d) {                                                                  \
        asm volatile("{\n\t.reg .pred P1;\n\t"                                  \
        "WL_%=:\n\t"                                                            \
        "mbarrier.try_wait.parity.acquire.cta.shared::cta.b64 P1, [%0], %1, 0x989680;\n\t" \
        "@P1 bra.uni WD_%=;\n\t"                                                \
        "bra.uni WL_%=;\n\t"                                                    \
        "WD_%=:\n\t}" :: "r"(_m), "r"(_p) : "memory");                          \
    }                                                                           \
} while (0)

#define BULK_G2S(dst, src, bytes, mbar) \
    asm volatile("cp.async.bulk.shared::cta.global.mbarrier::complete_tx::bytes [%0], [%1], %2, [%3];" \
        :: "r"(dst), "l"(src), "r"((uint32_t)(bytes)), "r"(mbar) : "memory")

__device__ __forceinline__ void ldsm4(uint32_t (&r)[4], uint32_t addr) {
    asm volatile("ldmatrix.sync.aligned.m8n8.x4.shared.b16 {%0,%1,%2,%3}, [%4];"
        : "=r"(r[0]), "=r"(r[1]), "=r"(r[2]), "=r"(r[3]) : "r"(addr));
}
__device__ __forceinline__ void mma16816(float (&c)[4], const uint32_t (&a)[4],
                                         uint32_t b0, uint32_t b1) {
    asm volatile(
        "mma.sync.aligned.m16n8k16.row.col.f32.f16.f16.f32 "
        "{%0,%1,%2,%3}, {%4,%5,%6,%7}, {%8,%9}, {%0,%1,%2,%3};"
        : "+f"(c[0]), "+f"(c[1]), "+f"(c[2]), "+f"(c[3])
        : "r"(a[0]), "r"(a[1]), "r"(a[2]), "r"(a[3]), "r"(b0), "r"(b1));
}

// ---------------- init ------------------------------------------------------
__global__ void init_kernel(float* __restrict__ out, const float* __restrict__ bv) {
    int i = blockIdx.x * blockDim.x + threadIdx.x;
    if (i < 262144) ((uint32_t*)&g_hT[0][0][0][0])[i] = 0u;   // zero h0 tiles
    if (i < ROWS) out[i] = bv[0];
    if (i < T_LEN) g_arr[i] = 0u;
}

// ---------------- obs -> fp16 swizzled tiles ---------------------------------
__global__ void obs_conv_kernel(const float* __restrict__ obs) {
    int i = blockIdx.x * blockDim.x + threadIdx.x;   // 8388608 threads
    int d = (i & 63) * 2;
    int r = i >> 6;
    int t = r >> 10, n = r & 1023;
    size_t off = (size_t)(n >> 3) * 131072 + (size_t)t * 1024 + (size_t)(n & 7) * 128 + d;
    float2 v = *(const float2*)(obs + off);
    __half h0 = __float2half_rn(v.x);
    __half h1 = __float2half_rn(v.y);
    uint32_t ph = (uint32_t)__half_as_ushort(h0) | ((uint32_t)__half_as_ushort(h1) << 16);
    int rt = r >> 7, mloc = r & 127, kt = d >> 6, c = d & 63;
    *(uint32_t*)((char*)&g_oT[rt][kt][0] + SW128((uint32_t)(mloc * 128 + c * 2))) = ph;
}

// ---------------- prep: split + tile/swizzle weights (fp16 hi/lo) -----------
__global__ void prep_kernel(const float* __restrict__ W_ih, const float* __restrict__ W_hh,
                            const float* __restrict__ W1) {
    int idx = blockIdx.x * blockDim.x + threadIdx.x;   // 786432
    if (idx >= G_DIM * H_DIM) return;
    int k = idx & 511, kt = k >> 6, c = k & 63;
    // W_ih -> [nt][kt] 128x64 tiles, hi/lo
    {
        int n = idx >> 9;
        int nt = n >> 7, m = n & 127;
        float v = W_ih[idx];
        __half hi = __float2half_rn(v);
        __half lo = __float2half_rn(v - __half2float(hi));
        uint32_t off = SW128((uint32_t)(m * 128 + c * 2));
        *(__half*)((char*)&g_WihT[0][nt][kt][0] + off) = hi;
        *(__half*)((char*)&g_WihT[1][nt][kt][0] + off) = lo;
    }
    // W_hh gate-triple reorder -> [jc][kt] 96x64 tiles, hi/lo
    {
        int jtr = idx >> 9;
        int jc = jtr / 96, rem = jtr % 96;
        int gt = rem >> 5, jl = rem & 31;
        float v = W_hh[(size_t)(gt * 512 + jc * 32 + jl) * H_DIM + k];
        __half hi = __float2half_rn(v);
        __half lo = __float2half_rn(v - __half2float(hi));
        uint32_t off = SW128((uint32_t)(rem * 128 + c * 2));
        *(__half*)((char*)&g_WhhT[0][jc][kt][0] + off) = hi;
        *(__half*)((char*)&g_WhhT[1][jc][kt][0] + off) = lo;
    }
    // W1 [512][128] -> [nt 4][kt 2] 128x64 tiles, hi/lo
    if (idx < 65536) {
        int n = idx >> 7, d = idx & 127;
        int nt = n >> 7, m = n & 127;
        int ktd = d >> 6, cd = d & 63;
        float v = W1[idx];
        __half hi = __float2half_rn(v);
        __half lo = __float2half_rn(v - __half2float(hi));
        uint32_t off = SW128((uint32_t)(m * 128 + cd * 2));
        *(__half*)((char*)&g_W1T[0][nt][ktd][0] + off) = hi;
        *(__half*)((char*)&g_W1T[1][nt][ktd][0] + off) = lo;
    }
}

// ---------------- gemm1: x = relu(obs @ W1^T + b1)  (fp16x2 HMMA) -----------
// grid (4 nt, 1024 rt). CTA 128m x 128n, K=128 (2 chunks), 2 fused passes.
__global__ __launch_bounds__(256, 2) void gemm1_kernel(const float* __restrict__ b1)
{
    extern __shared__ char smem[];
    const uint32_t sb = smem_u32(smem);
    const int tid = threadIdx.x;
    const int wid = tid >> 5, lane = tid & 31;
    const int mw = wid >> 1, nw = wid & 1;
    const int nt = blockIdx.x;
    const int rt = blockIdx.y;

    if (tid == 0) {
        MBAR_INIT(sb, 1);
        MBAR_INIT(sb + 8, 1);
        FENCE_ASYNC();
    }
    __syncthreads();

    float c[2][8][4] = {};

    if (tid == 0) {
#pragma unroll
        for (int ch = 0; ch < 2; ch++) {
            uint32_t mb = sb + ch * 8;
            uint32_t base = sb + 1024 + ch * 49152;
            MBAR_EXPECT(mb, 49152);
            BULK_G2S(base,         &g_oT[rt][ch][0],     16384, mb);
            BULK_G2S(base + 16384, &g_W1T[0][nt][ch][0], 16384, mb);
            BULK_G2S(base + 32768, &g_W1T[1][nt][ch][0], 16384, mb);
        }
    }

    for (int ch = 0; ch < 2; ch++) {
        MBAR_WAIT_PARITY(sb + ch * 8, 0);
        const uint32_t base = sb + 1024 + ch * 49152;
        const uint32_t sA = base, sBh = base + 16384, sBl = base + 32768;
#pragma unroll
        for (int ks = 0; ks < 4; ks++) {
            uint32_t a[2][4];
            uint32_t arow0 = mw * 32 + (lane & 15);
            uint32_t acol = ks * 16 + ((lane >> 4) << 3);
#pragma unroll
            for (int mi = 0; mi < 2; mi++)
                ldsm4(a[mi], sA + SW128((arow0 + mi * 16) * 128 + acol * 2));
#pragma unroll
            for (int bp = 0; bp < 4; bp++) {
                uint32_t bh[4], bl[4];
                uint32_t brow = nw * 64 + bp * 16 + (lane & 7) + ((lane >> 4) & 1) * 8;
                uint32_t bcol = ks * 16 + ((lane >> 3) & 1) * 8;
                uint32_t boff = SW128(brow * 128 + bcol * 2);
                ldsm4(bh, sBh + boff);
                ldsm4(bl, sBl + boff);
#pragma unroll
                for (int mi = 0; mi < 2; mi++) {
                    mma16816(c[mi][2 * bp],     a[mi], bh[0], bh[1]);
                    mma16816(c[mi][2 * bp + 1], a[mi], bh[2], bh[3]);
                    mma16816(c[mi][2 * bp],     a[mi], bl[0], bl[1]);
                    mma16816(c[mi][2 * bp + 1], a[mi], bl[2], bl[3]);
                }
            }
        }
    }

    // epilogue: relu + bias -> fp16 x tiles
    const int n0 = nt * 128;
    const int g = lane >> 2, ct = lane & 3;
#pragma unroll
    for (int mi = 0; mi < 2; mi++) {
#pragma unroll
        for (int ntl = 0; ntl < 8; ntl++) {
            int mloc = mw * 32 + mi * 16 + g;
            int col = n0 + nw * 64 + ntl * 8 + ct * 2;
            float2 bi = *(const float2*)(b1 + col);
            float v0x = fmaxf(c[mi][ntl][0] + bi.x, 0.0f);
            float v0y = fmaxf(c[mi][ntl][1] + bi.y, 0.0f);
            float v1x = fmaxf(c[mi][ntl][2] + bi.x, 0.0f);
            float v1y = fmaxf(c[mi][ntl][3] + bi.y, 0.0f);
            int kt = col >> 6, cc = col & 63;
            uint32_t p0 = (uint32_t)__half_as_ushort(__float2half_rn(v0x))
                        | ((uint32_t)__half_as_ushort(__float2half_rn(v0y)) << 16);
            uint32_t p1 = (uint32_t)__half_as_ushort(__float2half_rn(v1x))
                        | ((uint32_t)__half_as_ushort(__float2half_rn(v1y)) << 16);
            *(uint32_t*)((char*)&g_xT[rt][kt][0] + SW128((uint32_t)(mloc * 128 + cc * 2)))       = p0;
            *(uint32_t*)((char*)&g_xT[rt][kt][0] + SW128((uint32_t)((mloc + 8) * 128 + cc * 2))) = p1;
        }
    }
}

// ---------------- gemm2: gi = x @ W_ih^T + b_ih  (fp16x2, bulk loads) -------
__global__ __launch_bounds__(256, 2) void gemm2_kernel(const float* __restrict__ b_ih)
{
    extern __shared__ char smem[];
    const uint32_t sb = smem_u32(smem);
    const int tid = threadIdx.x;
    const int wid = tid >> 5, lane = tid & 31;
    const int mw = wid >> 1, nw = wid & 1;
    const int nt = blockIdx.x;
    const int rt = blockIdx.y;

    if (tid == 0) {
        MBAR_INIT(sb, 1);
        MBAR_INIT(sb + 8, 1);
        FENCE_ASYNC();
    }
    __syncthreads();

    float c[2][8][4] = {};

    auto issue = [&](int ch, int buf) {
        uint32_t mb = sb + buf * 8;
        uint32_t base = sb + 1024 + buf * 49152;
        MBAR_EXPECT(mb, 49152);
        BULK_G2S(base,         &g_xT[rt][ch][0],      16384, mb);
        BULK_G2S(base + 16384, &g_WihT[0][nt][ch][0], 16384, mb);
        BULK_G2S(base + 32768, &g_WihT[1][nt][ch][0], 16384, mb);
    };

    if (tid == 0) { issue(0, 0); issue(1, 1); }

    for (int ch = 0; ch < 8; ch++) {
        const int buf = ch & 1;
        MBAR_WAIT_PARITY(sb + buf * 8, (ch >> 1) & 1);
        const uint32_t base = sb + 1024 + buf * 49152;
        const uint32_t sA = base, sBh = base + 16384, sBl = base + 32768;

#pragma unroll
        for (int ks = 0; ks < 4; ks++) {
            uint32_t a[2][4];
            uint32_t arow0 = mw * 32 + (lane & 15);
            uint32_t acol = ks * 16 + ((lane >> 4) << 3);
#pragma unroll
            for (int mi = 0; mi < 2; mi++)
                ldsm4(a[mi], sA + SW128((arow0 + mi * 16) * 128 + acol * 2));
#pragma unroll
            for (int bp = 0; bp < 4; bp++) {
                uint32_t bh[4], bl[4];
                uint32_t brow = nw * 64 + bp * 16 + (lane & 7) + ((lane >> 4) & 1) * 8;
                uint32_t bcol = ks * 16 + ((lane >> 3) & 1) * 8;
                uint32_t boff = SW128(brow * 128 + bcol * 2);
                ldsm4(bh, sBh + boff);
                ldsm4(bl, sBl + boff);
#pragma unroll
                for (int mi = 0; mi < 2; mi++) {
                    mma16816(c[mi][2 * bp],     a[mi], bh[0], bh[1]);
                    mma16816(c[mi][2 * bp + 1], a[mi], bh[2], bh[3]);
                    mma16816(c[mi][2 * bp],     a[mi], bl[0], bl[1]);
                    mma16816(c[mi][2 * bp + 1], a[mi], bl[2], bl[3]);
                }
            }
        }
        __syncthreads();
        if (tid == 0 && ch + 2 < 8) issue(ch + 2, buf);
    }

    // epilogue
    const int r0 = rt * 128, n0 = nt * 128;
    const int g = lane >> 2, ct = lane & 3;
#pragma unroll
    for (int mi = 0; mi < 2; mi++) {
#pragma unroll
        for (int ntl = 0; ntl < 8; ntl++) {
            int m = r0 + mw * 32 + mi * 16 + g;
            int n = n0 + nw * 64 + ntl * 8 + ct * 2;
            float2 bi = *(const float2*)(b_ih + n);
            float2 v0, v1;
            v0.x = c[mi][ntl][0] + bi.x; v0.y = c[mi][ntl][1] + bi.y;
            v1.x = c[mi][ntl][2] + bi.x; v1.y = c[mi][ntl][3] + bi.y;
            *(float2*)(g_gi + (size_t)m * G_DIM + n)       = v0;
            *(float2*)(g_gi + (size_t)(m + 8) * G_DIM + n) = v1;
        }
    }
}

// ---------------- persistent GRU scan ---------------------------------------
__global__ __launch_bounds__(256, 1) void gru_persist_kernel(
    const float* __restrict__ b_hh, const float* __restrict__ Wv,
    float* __restrict__ out)
{
    extern __shared__ char smem[];
    const uint32_t sb = smem_u32(smem);
    const int tid = threadIdx.x;
    const int wid = tid >> 5, lane = tid & 31;
    const int jc = blockIdx.x;    // 0..15
    const int mt = blockIdx.y;    // 0..7

    const uint32_t mbA0 = sb, mbA1 = sb + 8, mbW = sb + 16;
    const uint32_t A0 = sb + 1024, A1 = sb + 17408, W0 = sb + 33792;

    if (tid == 0) {
        MBAR_INIT(mbA0, 1);
        MBAR_INIT(mbA1, 1);
        MBAR_INIT(mbW, 1);
        FENCE_ASYNC();
    }
    __syncthreads();

    if (tid == 0) {
        MBAR_EXPECT(mbW, 196608);
#pragma unroll
        for (int ch = 0; ch < 8; ch++) {
            BULK_G2S(W0 + ch * 24576,         &g_WhhT[0][jc][ch][0], 12288, mbW);
            BULK_G2S(W0 + ch * 24576 + 12288, &g_WhhT[1][jc][ch][0], 12288, mbW);
        }
    }

    // per-thread constants
    const int g = lane >> 2, ct = lane & 3;
    const int jbase = jc * 32;
    float2 brv[4], bzv[4], bnv[4], wvv[4];
#pragma unroll
    for (int jj = 0; jj < 4; jj++) {
        int j = jbase + jj * 8 + ct * 2;
        brv[jj] = *(const float2*)(b_hh + j);
        bzv[jj] = *(const float2*)(b_hh + 512 + j);
        bnv[jj] = *(const float2*)(b_hh + 1024 + j);
        wvv[jj] = *(const float2*)(Wv + j);
    }
    float hreg[2][4][2];
#pragma unroll
    for (int mi = 0; mi < 2; mi++)
#pragma unroll
        for (int jj = 0; jj < 4; jj++)
            hreg[mi][jj][0] = hreg[mi][jj][1] = 0.0f;

    MBAR_WAIT_PARITY(mbW, 0);

    int pA0 = 0, pA1 = 0;

    for (int t = 0; t < T_LEN; t++) {
        const int rd = t & 1, wr = (t + 1) & 1;
        if (tid == 0) {
            MBAR_EXPECT(mbA0, 16384);
            BULK_G2S(A0, &g_hT[rd][mt][0][0], 16384, mbA0);
            MBAR_EXPECT(mbA1, 16384);
            BULK_G2S(A1, &g_hT[rd][mt][1][0], 16384, mbA1);
        }

        // preload this step's gi slice into registers (consumed in epilogue)
        const float* gi_t = g_gi + ((size_t)t * NB + mt * 128) * G_DIM;
        float2 giR[2][4], giZ[2][4], giN[2][4];
#pragma unroll
        for (int mi = 0; mi < 2; mi++) {
            int mloc = wid * 16 + g + mi * 8;
            const float* row = gi_t + (size_t)mloc * G_DIM;
#pragma unroll
            for (int jj = 0; jj < 4; jj++) {
                int j = jbase + jj * 8 + ct * 2;
                giR[mi][jj] = *(const float2*)(row + j);
                giZ[mi][jj] = *(const float2*)(row + 512 + j);
                giN[mi][jj] = *(const float2*)(row + 1024 + j);
            }
        }

        float c[12][4] = {};

        for (int ch = 0; ch < 8; ch++) {
            const uint32_t mb = (ch & 1) ? mbA1 : mbA0;
            const uint32_t Ab = (ch & 1) ? A1 : A0;
            if (ch & 1) { MBAR_WAIT_PARITY(mb, pA1); pA1 ^= 1; }
            else        { MBAR_WAIT_PARITY(mb, pA0); pA0 ^= 1; }
            const uint32_t Wc = W0 + ch * 24576;
#pragma unroll
            for (int ks = 0; ks < 4; ks++) {
                uint32_t a[4];
                uint32_t arow = wid * 16 + (lane & 15);
                uint32_t acol = ks * 16 + ((lane >> 4) << 3);
                ldsm4(a, Ab + SW128(arow * 128 + acol * 2));
#pragma unroll
                for (int bt = 0; bt < 6; bt++) {
                    uint32_t bh[4], bl[4];
                    uint32_t brow = bt * 16 + (lane & 7) + ((lane >> 4) & 1) * 8;
                    uint32_t bcol = ks * 16 + ((lane >> 3) & 1) * 8;
                    uint32_t boff = SW128(brow * 128 + bcol * 2);
                    ldsm4(bh, Wc + boff);
                    ldsm4(bl, Wc + 12288 + boff);
                    mma16816(c[2 * bt],     a, bh[0], bh[1]);
                    mma16816(c[2 * bt + 1], a, bh[2], bh[3]);
                    mma16816(c[2 * bt],     a, bl[0], bl[1]);
                    mma16816(c[2 * bt + 1], a, bl[2], bl[3]);
                }
            }
            __syncthreads();
            if (tid == 0 && ch + 2 < 8) {
                MBAR_EXPECT(mb, 16384);
                BULK_G2S(Ab, &g_hT[rd][mt][ch + 2][0], 16384, mb);
            }
        }

        // ---------------- fused epilogue ----------------
#pragma unroll
        for (int mi = 0; mi < 2; mi++) {
            int mloc = wid * 16 + g + mi * 8;
            int m_g = mt * 128 + mloc;

            float vp = 0.0f;
#pragma unroll
            for (int jj = 0; jj < 4; jj++) {
                int jl = jj * 8 + ct * 2;
                int j  = jbase + jl;

                float r0 = sigf(giR[mi][jj].x + brv[jj].x + c[jj][mi * 2]);
                float r1 = sigf(giR[mi][jj].y + brv[jj].y + c[jj][mi * 2 + 1]);
                float z0 = sigf(giZ[mi][jj].x + bzv[jj].x + c[4 + jj][mi * 2]);
                float z1 = sigf(giZ[mi][jj].y + bzv[jj].y + c[4 + jj][mi * 2 + 1]);
                float nt0 = tanhfast(giN[mi][jj].x + r0 * (c[8 + jj][mi * 2] + bnv[jj].x));
                float nt1 = tanhfast(giN[mi][jj].y + r1 * (c[8 + jj][mi * 2 + 1] + bnv[jj].y));
                float h0 = (1.0f - z0) * nt0 + z0 * hreg[mi][jj][0];
                float h1 = (1.0f - z1) * nt1 + z1 * hreg[mi][jj][1];
                hreg[mi][jj][0] = h0;
                hreg[mi][jj][1] = h1;

                __half hh0 = __float2half_rn(h0);
                __half hh1 = __float2half_rn(h1);
                uint32_t ph = (uint32_t)__half_as_ushort(hh0) | ((uint32_t)__half_as_ushort(hh1) << 16);
                int kt = j >> 6, cc = j & 63;
                uint32_t off = SW128((uint32_t)(mloc * 128 + cc * 2));
                *(uint32_t*)((char*)&g_hT[wr][mt][kt][0] + off) = ph;

                vp = fmaf(wvv[jj].x, h0, vp);
                vp = fmaf(wvv[jj].y, h1, vp);
            }
            vp += __shfl_xor_sync(0xffffffffu, vp, 1);
            vp += __shfl_xor_sync(0xffffffffu, vp, 2);
            if (ct == 0) {
                int bs = m_g >> 3, a = m_g & 7;
                atomicAdd(&out[((size_t)bs * T_LEN + t) * 8 + a], vp);
            }
        }

        // ---------------- one-hop grid barrier ----------------
        if (t < T_LEN - 1) {
            __threadfence();
            __syncthreads();
            if (tid == 0) {
                atomicAdd(&g_arr[t], 1u);
                while (((volatile unsigned*)g_arr)[t] < 128u) { }
                __threadfence();
            }
            __syncthreads();
        }
    }
}

// ---------------------------------------------------------------------------
extern "C" void kernel_launch(void* const* d_in, const int* in_sizes, int n_in,
                              void* d_out, int out_size)
{
    const float* obs  = (const float*)d_in[0];
    const float* W1   = (const float*)d_in[1];
    const float* b1   = (const float*)d_in[2];
    const float* W_ih = (const float*)d_in[3];
    const float* b_ih = (const float*)d_in[4];
    const float* W_hh = (const float*)d_in[5];
    const float* b_hh = (const float*)d_in[6];
    const float* Wv   = (const float*)d_in[7];
    const float* bv   = (const float*)d_in[8];
    float* out = (float*)d_out;

    cudaFuncSetAttribute(gemm1_kernel,       cudaFuncAttributeMaxDynamicSharedMemorySize, 99328);
    cudaFuncSetAttribute(gemm2_kernel,       cudaFuncAttributeMaxDynamicSharedMemorySize, 99328);
    cudaFuncSetAttribute(gru_persist_kernel, cudaFuncAttributeMaxDynamicSharedMemorySize, 230400);

    init_kernel<<<2048, 256>>>(out, bv);
    obs_conv_kernel<<<32768, 256>>>(obs);
    prep_kernel<<<3072, 256>>>(W_ih, W_hh, W1);
    gemm1_kernel<<<dim3(4, 1024), 256, 99328>>>(b1);
    gemm2_kernel<<<dim3(12, 1024), 256, 99328>>>(b_ih);
    gru_persist_kernel<<<dim3(16, 8), 256, 230400>>>(b_hh, Wv, out);
}

// round 7
// speedup vs baseline: 5.4217x; 1.0350x over previous
#include <cuda_runtime.h>
#include <cuda_fp16.h>
#include <math.h>
#include <stdint.h>

#define T_LEN 128
#define NB    1024
#define D_IN  128
#define H_DIM 512
#define G_DIM 1536
#define ROWS  (T_LEN * NB)     // 131072

// ---------------- scratch (__device__ globals) ------------------------------
__device__ __half g_oT[1024][2][8192];        // obs fp16 tiles [rt][kt] 128x64, SW128
__device__ __half g_W1T[2][4][2][8192];       // W1 hi/lo tiles [nt][kt] 128x64
__device__ __half g_xT[1024][8][8192];        // x fp16 tiles [rt][kt] 128x64, SW128
__device__ __half g_WihT[16][8][2][6144];     // W_ih [jc][kt][hi/lo] 96x64 gate-triple
__device__ __half g_WhhT[16][8][2][6144];     // W_hh [jc][kt][hi/lo] 96x64 gate-triple
__device__ __half g_hT[2][8][8][8192];        // h fp16 tiles ping-pong [mt][kt] 128x64
__device__ unsigned g_arrm[8][T_LEN];         // per-mt, per-step barrier counters

__device__ __forceinline__ float sigf(float x) {
    return __fdividef(1.0f, 1.0f + __expf(-x));
}
__device__ __forceinline__ float tanhfast(float x) {
    return 2.0f * sigf(2.0f * x) - 1.0f;
}

#define SW128(off) ((off) ^ (((off) >> 3) & 0x70))

__device__ __forceinline__ uint32_t smem_u32(const void* p) {
    uint32_t a;
    asm("{ .reg .u64 t; cvta.to.shared.u64 t, %1; cvt.u32.u64 %0, t; }" : "=r"(a) : "l"(p));
    return a;
}

#define MBAR_INIT(addr, cnt) \
    asm volatile("mbarrier.init.shared.b64 [%0], %1;" :: "r"(addr), "r"(cnt) : "memory")
#define MBAR_EXPECT(addr, bytes) \
    asm volatile("mbarrier.arrive.expect_tx.shared.b64 _, [%0], %1;" :: "r"(addr), "r"(bytes) : "memory")
#define FENCE_ASYNC() asm volatile("fence.proxy.async.shared::cta;" ::: "memory")

#define MBAR_WAIT_PARITY(addr, par) do {                                        \
    uint32_t _m = (addr); uint32_t _p = (par); uint32_t _d;                     \
    asm volatile("{\n\t.reg .pred p;\n\t"                                       \
        "mbarrier.try_wait.parity.acquire.cta.shared::cta.b64 p, [%1], %2;\n\t" \
        "selp.b32 %0, 1, 0, p;\n\t}" : "=r"(_d) : "r"(_m), "r"(_p) : "memory"); \
    if (!_d) {                                                                  \
        asm volatile("{\n\t.reg .pred P1;\n\t"                                  \
        "WL_%=:\n\t"                                                            \
        "mbarrier.try_wait.parity.acquire.cta.shared::cta.b64 P1, [%0], %1, 0x989680;\n\t" \
        "@P1 bra.uni WD_%=;\n\t"                                                \
        "bra.uni WL_%=;\n\t"                                                    \
        "WD_%=:\n\t}" :: "r"(_m), "r"(_p) : "memory");                          \
    }                                                                           \
} while (0)

#define BULK_G2S(dst, src, bytes, mbar) \
    asm volatile("cp.async.bulk.shared::cta.global.mbarrier::complete_tx::bytes [%0], [%1], %2, [%3];" \
        :: "r"(dst), "l"(src), "r"((uint32_t)(bytes)), "r"(mbar) : "memory")

__device__ __forceinline__ void ldsm4(uint32_t (&r)[4], uint32_t addr) {
    asm volatile("ldmatrix.sync.aligned.m8n8.x4.shared.b16 {%0,%1,%2,%3}, [%4];"
        : "=r"(r[0]), "=r"(r[1]), "=r"(r[2]), "=r"(r[3]) : "r"(addr));
}
__device__ __forceinline__ void mma16816(float (&c)[4], const uint32_t (&a)[4],
                                         uint32_t b0, uint32_t b1) {
    asm volatile(
        "mma.sync.aligned.m16n8k16.row.col.f32.f16.f16.f32 "
        "{%0,%1,%2,%3}, {%4,%5,%6,%7}, {%8,%9}, {%0,%1,%2,%3};"
        : "+f"(c[0]), "+f"(c[1]), "+f"(c[2]), "+f"(c[3])
        : "r"(a[0]), "r"(a[1]), "r"(a[2]), "r"(a[3]), "r"(b0), "r"(b1));
}

// ---------------- init ------------------------------------------------------
__global__ void init_kernel(float* __restrict__ out, const float* __restrict__ bv) {
    int i = blockIdx.x * blockDim.x + threadIdx.x;
    if (i < 262144) ((uint32_t*)&g_hT[0][0][0][0])[i] = 0u;   // zero h0 tiles
    if (i < ROWS) out[i] = bv[0];
    if (i < 8 * T_LEN) ((unsigned*)g_arrm)[i] = 0u;
}

// ---------------- obs -> fp16 swizzled tiles ---------------------------------
__global__ void obs_conv_kernel(const float* __restrict__ obs) {
    int i = blockIdx.x * blockDim.x + threadIdx.x;
    int d = (i & 63) * 2;
    int r = i >> 6;
    int t = r >> 10, n = r & 1023;
    size_t off = (size_t)(n >> 3) * 131072 + (size_t)t * 1024 + (size_t)(n & 7) * 128 + d;
    float2 v = *(const float2*)(obs + off);
    __half h0 = __float2half_rn(v.x);
    __half h1 = __float2half_rn(v.y);
    uint32_t ph = (uint32_t)__half_as_ushort(h0) | ((uint32_t)__half_as_ushort(h1) << 16);
    int rt = r >> 7, mloc = r & 127, kt = d >> 6, c = d & 63;
    *(uint32_t*)((char*)&g_oT[rt][kt][0] + SW128((uint32_t)(mloc * 128 + c * 2))) = ph;
}

// ---------------- prep: gate-triple reorder + hi/lo split -------------------
__global__ void prep_kernel(const float* __restrict__ W_ih, const float* __restrict__ W_hh,
                            const float* __restrict__ W1) {
    int idx = blockIdx.x * blockDim.x + threadIdx.x;   // 786432
    if (idx >= G_DIM * H_DIM) return;
    int k = idx & 511, kt = k >> 6, c = k & 63;
    int jtr = idx >> 9;
    int jc = jtr / 96, rem = jtr % 96;
    int gt = rem >> 5, jl = rem & 31;
    size_t srow = (size_t)(gt * 512 + jc * 32 + jl);
    uint32_t off = SW128((uint32_t)(rem * 128 + c * 2));
    {
        float v = W_hh[srow * H_DIM + k];
        __half hi = __float2half_rn(v);
        __half lo = __float2half_rn(v - __half2float(hi));
        *(__half*)((char*)&g_WhhT[jc][kt][0][0] + off) = hi;
        *(__half*)((char*)&g_WhhT[jc][kt][1][0] + off) = lo;
    }
    {
        float v = W_ih[srow * H_DIM + k];
        __half hi = __float2half_rn(v);
        __half lo = __float2half_rn(v - __half2float(hi));
        *(__half*)((char*)&g_WihT[jc][kt][0][0] + off) = hi;
        *(__half*)((char*)&g_WihT[jc][kt][1][0] + off) = lo;
    }
    // W1 [512][128] -> [nt 4][kt 2] 128x64 tiles, hi/lo
    if (idx < 65536) {
        int n = idx >> 7, d = idx & 127;
        int nt = n >> 7, m = n & 127;
        int ktd = d >> 6, cd = d & 63;
        float v = W1[idx];
        __half hi = __float2half_rn(v);
        __half lo = __float2half_rn(v - __half2float(hi));
        uint32_t o2 = SW128((uint32_t)(m * 128 + cd * 2));
        *(__half*)((char*)&g_W1T[0][nt][ktd][0] + o2) = hi;
        *(__half*)((char*)&g_W1T[1][nt][ktd][0] + o2) = lo;
    }
}

// ---------------- gemm1: x = relu(obs @ W1^T + b1)  (fp16x2 HMMA) -----------
__global__ __launch_bounds__(256, 2) void gemm1_kernel(const float* __restrict__ b1)
{
    extern __shared__ char smem[];
    const uint32_t sb = smem_u32(smem);
    const int tid = threadIdx.x;
    const int wid = tid >> 5, lane = tid & 31;
    const int mw = wid >> 1, nw = wid & 1;
    const int nt = blockIdx.x;
    const int rt = blockIdx.y;

    if (tid == 0) {
        MBAR_INIT(sb, 1);
        MBAR_INIT(sb + 8, 1);
        FENCE_ASYNC();
    }
    __syncthreads();

    float c[2][8][4] = {};

    if (tid == 0) {
#pragma unroll
        for (int ch = 0; ch < 2; ch++) {
            uint32_t mb = sb + ch * 8;
            uint32_t base = sb + 1024 + ch * 49152;
            MBAR_EXPECT(mb, 49152);
            BULK_G2S(base,         &g_oT[rt][ch][0],     16384, mb);
            BULK_G2S(base + 16384, &g_W1T[0][nt][ch][0], 16384, mb);
            BULK_G2S(base + 32768, &g_W1T[1][nt][ch][0], 16384, mb);
        }
    }

    for (int ch = 0; ch < 2; ch++) {
        MBAR_WAIT_PARITY(sb + ch * 8, 0);
        const uint32_t base = sb + 1024 + ch * 49152;
        const uint32_t sA = base, sBh = base + 16384, sBl = base + 32768;
#pragma unroll
        for (int ks = 0; ks < 4; ks++) {
            uint32_t a[2][4];
            uint32_t arow0 = mw * 32 + (lane & 15);
            uint32_t acol = ks * 16 + ((lane >> 4) << 3);
#pragma unroll
            for (int mi = 0; mi < 2; mi++)
                ldsm4(a[mi], sA + SW128((arow0 + mi * 16) * 128 + acol * 2));
#pragma unroll
            for (int bp = 0; bp < 4; bp++) {
                uint32_t bh[4], bl[4];
                uint32_t brow = nw * 64 + bp * 16 + (lane & 7) + ((lane >> 4) & 1) * 8;
                uint32_t bcol = ks * 16 + ((lane >> 3) & 1) * 8;
                uint32_t boff = SW128(brow * 128 + bcol * 2);
                ldsm4(bh, sBh + boff);
                ldsm4(bl, sBl + boff);
#pragma unroll
                for (int mi = 0; mi < 2; mi++) {
                    mma16816(c[mi][2 * bp],     a[mi], bh[0], bh[1]);
                    mma16816(c[mi][2 * bp + 1], a[mi], bh[2], bh[3]);
                    mma16816(c[mi][2 * bp],     a[mi], bl[0], bl[1]);
                    mma16816(c[mi][2 * bp + 1], a[mi], bl[2], bl[3]);
                }
            }
        }
    }

    const int n0 = nt * 128;
    const int g = lane >> 2, ct = lane & 3;
#pragma unroll
    for (int mi = 0; mi < 2; mi++) {
#pragma unroll
        for (int ntl = 0; ntl < 8; ntl++) {
            int mloc = mw * 32 + mi * 16 + g;
            int col = n0 + nw * 64 + ntl * 8 + ct * 2;
            float2 bi = *(const float2*)(b1 + col);
            float v0x = fmaxf(c[mi][ntl][0] + bi.x, 0.0f);
            float v0y = fmaxf(c[mi][ntl][1] + bi.y, 0.0f);
            float v1x = fmaxf(c[mi][ntl][2] + bi.x, 0.0f);
            float v1y = fmaxf(c[mi][ntl][3] + bi.y, 0.0f);
            int kt = col >> 6, cc = col & 63;
            uint32_t p0 = (uint32_t)__half_as_ushort(__float2half_rn(v0x))
                        | ((uint32_t)__half_as_ushort(__float2half_rn(v0y)) << 16);
            uint32_t p1 = (uint32_t)__half_as_ushort(__float2half_rn(v1x))
                        | ((uint32_t)__half_as_ushort(__float2half_rn(v1y)) << 16);
            *(uint32_t*)((char*)&g_xT[rt][kt][0] + SW128((uint32_t)(mloc * 128 + cc * 2)))       = p0;
            *(uint32_t*)((char*)&g_xT[rt][kt][0] + SW128((uint32_t)((mloc + 8) * 128 + cc * 2))) = p1;
        }
    }
}

// ---------------- fused persistent GRU scan ---------------------------------
// grid (16 jc, 8 mt). Per step, each CTA computes BOTH gh = h@W_hh^T and
// gi = x_t@W_ih^T (128m x 96 gate-triple, K=512, fp16 hi/lo weights),
// streaming h/x/W_hh/W_ih chunks from L2 via cp.async.bulk.
// SMEM stage (80KB): h@0, x@16K, Whh@32K(hi/lo 24K), Wih@57344(24K); 2 stages.
// total = 1024 + 163840 = 164864 bytes.
#define STG_STRIDE 81920
#define OFF_X  16384
#define OFF_WH 32768
#define OFF_WI 57344

__global__ __launch_bounds__(256, 1) void gru_persist_kernel(
    const float* __restrict__ b_hh, const float* __restrict__ b_ih,
    const float* __restrict__ Wv, float* __restrict__ out)
{
    extern __shared__ char smem[];
    const uint32_t sb = smem_u32(smem);
    const int tid = threadIdx.x;
    const int wid = tid >> 5, lane = tid & 31;
    const int jc = blockIdx.x;    // 0..15
    const int mt = blockIdx.y;    // 0..7

    // mbars: h-mbar[2] @ sb+0/8, xw-mbar[2] @ sb+16/24
    if (tid == 0) {
        MBAR_INIT(sb, 1);
        MBAR_INIT(sb + 8, 1);
        MBAR_INIT(sb + 16, 1);
        MBAR_INIT(sb + 24, 1);
        FENCE_ASYNC();
    }
    __syncthreads();

    const uint32_t S0 = sb + 1024;

    // per-thread constants
    const int g = lane >> 2, ct = lane & 3;
    const int jbase = jc * 32;
    float2 brv[4], bzv[4], bniv[4], bnhv[4], wvv[4];
#pragma unroll
    for (int jj = 0; jj < 4; jj++) {
        int j = jbase + jj * 8 + ct * 2;
        float2 ir = *(const float2*)(b_ih + j);
        float2 hr = *(const float2*)(b_hh + j);
        brv[jj].x = ir.x + hr.x; brv[jj].y = ir.y + hr.y;        // combined r bias
        float2 iz = *(const float2*)(b_ih + 512 + j);
        float2 hz = *(const float2*)(b_hh + 512 + j);
        bzv[jj].x = iz.x + hz.x; bzv[jj].y = iz.y + hz.y;        // combined z bias
        bniv[jj] = *(const float2*)(b_ih + 1024 + j);
        bnhv[jj] = *(const float2*)(b_hh + 1024 + j);
        wvv[jj]  = *(const float2*)(Wv + j);
    }
    float hreg[2][4][2];
#pragma unroll
    for (int mi = 0; mi < 2; mi++)
#pragma unroll
        for (int jj = 0; jj < 4; jj++)
            hreg[mi][jj][0] = hreg[mi][jj][1] = 0.0f;

    int pH[2] = {0, 0}, pX[2] = {0, 0};

    // issue helpers (tid 0 only)
    auto issueH = [&](int t, int ch, int buf) {
        uint32_t mb = sb + buf * 8;
        MBAR_EXPECT(mb, 16384);
        BULK_G2S(S0 + buf * STG_STRIDE, &g_hT[t & 1][mt][ch][0], 16384, mb);
    };
    auto issueXW = [&](int t, int ch, int buf) {
        uint32_t mb = sb + 16 + buf * 8;
        uint32_t base = S0 + buf * STG_STRIDE;
        MBAR_EXPECT(mb, 65536);
        BULK_G2S(base + OFF_X,  &g_xT[t * 8 + mt][ch][0], 16384, mb);
        BULK_G2S(base + OFF_WH, &g_WhhT[jc][ch][0][0],    24576, mb);
        BULK_G2S(base + OFF_WI, &g_WihT[jc][ch][0][0],    24576, mb);
    };

    if (tid == 0) {
        issueXW(0, 0, 0); issueH(0, 0, 0);
        issueXW(0, 1, 1); issueH(0, 1, 1);
    }

    for (int t = 0; t < T_LEN; t++) {
        float cg[12][4] = {};   // gh accumulators
        float ci[12][4] = {};   // gi accumulators

        for (int ch = 0; ch < 8; ch++) {
            const int buf = ch & 1;
            MBAR_WAIT_PARITY(sb + buf * 8, pH[buf]);       pH[buf] ^= 1;
            MBAR_WAIT_PARITY(sb + 16 + buf * 8, pX[buf]);  pX[buf] ^= 1;
            const uint32_t base = S0 + buf * STG_STRIDE;

#pragma unroll
            for (int ks = 0; ks < 4; ks++) {
                uint32_t ah[4], ax[4];
                uint32_t arow = wid * 16 + (lane & 15);
                uint32_t acol = ks * 16 + ((lane >> 4) << 3);
                uint32_t aoff = SW128(arow * 128 + acol * 2);
                ldsm4(ah, base + aoff);
                ldsm4(ax, base + OFF_X + aoff);
#pragma unroll
                for (int bt = 0; bt < 6; bt++) {
                    uint32_t whh[4], wlh[4], whi[4], wli[4];
                    uint32_t brow = bt * 16 + (lane & 7) + ((lane >> 4) & 1) * 8;
                    uint32_t bcol = ks * 16 + ((lane >> 3) & 1) * 8;
                    uint32_t boff = SW128(brow * 128 + bcol * 2);
                    ldsm4(whh, base + OFF_WH + boff);
                    ldsm4(wlh, base + OFF_WH + 12288 + boff);
                    ldsm4(whi, base + OFF_WI + boff);
                    ldsm4(wli, base + OFF_WI + 12288 + boff);
                    mma16816(cg[2 * bt],     ah, whh[0], whh[1]);
                    mma16816(cg[2 * bt + 1], ah, whh[2], whh[3]);
                    mma16816(cg[2 * bt],     ah, wlh[0], wlh[1]);
                    mma16816(cg[2 * bt + 1], ah, wlh[2], wlh[3]);
                    mma16816(ci[2 * bt],     ax, whi[0], whi[1]);
                    mma16816(ci[2 * bt + 1], ax, whi[2], whi[3]);
                    mma16816(ci[2 * bt],     ax, wli[0], wli[1]);
                    mma16816(ci[2 * bt + 1], ax, wli[2], wli[3]);
                }
            }
            __syncthreads();
            if (tid == 0) {
                if (ch + 2 < 8) {
                    issueH(t, ch + 2, buf);
                    issueXW(t, ch + 2, buf);
                } else if (t + 1 < T_LEN) {
                    issueXW(t + 1, ch + 2 - 8, buf);   // cross-step x/W prefetch
                }
            }
        }

        // ---------------- fused epilogue ----------------
        const int wr = (t + 1) & 1;
#pragma unroll
        for (int mi = 0; mi < 2; mi++) {
            int mloc = wid * 16 + g + mi * 8;
            int m_g = mt * 128 + mloc;

            float vp = 0.0f;
#pragma unroll
            for (int jj = 0; jj < 4; jj++) {
                int jl = jj * 8 + ct * 2;
                int j  = jbase + jl;

                float r0 = sigf(ci[jj][mi * 2]     + cg[jj][mi * 2]     + brv[jj].x);
                float r1 = sigf(ci[jj][mi * 2 + 1] + cg[jj][mi * 2 + 1] + brv[jj].y);
                float z0 = sigf(ci[4 + jj][mi * 2]     + cg[4 + jj][mi * 2]     + bzv[jj].x);
                float z1 = sigf(ci[4 + jj][mi * 2 + 1] + cg[4 + jj][mi * 2 + 1] + bzv[jj].y);
                float nt0 = tanhfast(ci[8 + jj][mi * 2]     + bniv[jj].x
                                     + r0 * (cg[8 + jj][mi * 2]     + bnhv[jj].x));
                float nt1 = tanhfast(ci[8 + jj][mi * 2 + 1] + bniv[jj].y
                                     + r1 * (cg[8 + jj][mi * 2 + 1] + bnhv[jj].y));
                float h0 = (1.0f - z0) * nt0 + z0 * hreg[mi][jj][0];
                float h1 = (1.0f - z1) * nt1 + z1 * hreg[mi][jj][1];
                hreg[mi][jj][0] = h0;
                hreg[mi][jj][1] = h1;

                __half hh0 = __float2half_rn(h0);
                __half hh1 = __float2half_rn(h1);
                uint32_t ph = (uint32_t)__half_as_ushort(hh0) | ((uint32_t)__half_as_ushort(hh1) << 16);
                int kt = j >> 6, cc = j & 63;
                uint32_t off = SW128((uint32_t)(mloc * 128 + cc * 2));
                *(uint32_t*)((char*)&g_hT[wr][mt][kt][0] + off) = ph;

                vp = fmaf(wvv[jj].x, h0, vp);
                vp = fmaf(wvv[jj].y, h1, vp);
            }
            vp += __shfl_xor_sync(0xffffffffu, vp, 1);
            vp += __shfl_xor_sync(0xffffffffu, vp, 2);
            if (ct == 0) {
                int bs = m_g >> 3, a = m_g & 7;
                atomicAdd(&out[((size_t)bs * T_LEN + t) * 8 + a], vp);
            }
        }

        // ---------------- per-mt grid barrier (16 arrivals) ----------------
        if (t < T_LEN - 1) {
            __threadfence();
            __syncthreads();
            if (tid == 0) {
                atomicAdd(&g_arrm[mt][t], 1u);
                while (((volatile unsigned*)g_arrm[mt])[t] < 16u) { }
                __threadfence();
                issueH(t + 1, 0, 0);
                issueH(t + 1, 1, 1);
            }
            __syncthreads();
        }
    }
}

// ---------------------------------------------------------------------------
extern "C" void kernel_launch(void* const* d_in, const int* in_sizes, int n_in,
                              void* d_out, int out_size)
{
    const float* obs  = (const float*)d_in[0];
    const float* W1   = (const float*)d_in[1];
    const float* b1   = (const float*)d_in[2];
    const float* W_ih = (const float*)d_in[3];
    const float* b_ih = (const float*)d_in[4];
    const float* W_hh = (const float*)d_in[5];
    const float* b_hh = (const float*)d_in[6];
    const float* Wv   = (const float*)d_in[7];
    const float* bv   = (const float*)d_in[8];
    float* out = (float*)d_out;

    cudaFuncSetAttribute(gemm1_kernel,       cudaFuncAttributeMaxDynamicSharedMemorySize, 99328);
    cudaFuncSetAttribute(gru_persist_kernel, cudaFuncAttributeMaxDynamicSharedMemorySize, 164864);

    init_kernel<<<2048, 256>>>(out, bv);
    obs_conv_kernel<<<32768, 256>>>(obs);
    prep_kernel<<<3072, 256>>>(W_ih, W_hh, W1);
    gemm1_kernel<<<dim3(4, 1024), 256, 99328>>>(b1);
    gru_persist_kernel<<<dim3(16, 8), 256, 164864>>>(b_hh, b_ih, Wv, out);
}

// round 8
// speedup vs baseline: 8.5093x; 1.5695x over previous
#include <cuda_runtime.h>
#include <cuda_fp16.h>
#include <math.h>
#include <stdint.h>

#define T_LEN 128
#define NB    1024
#define D_IN  128
#define H_DIM 512
#define G_DIM 1536
#define ROWS  (T_LEN * NB)     // 131072

// ---------------- scratch (__device__ globals) ------------------------------
__device__ __half g_oT[1024][2][8192];      // obs fp16 tiles [rt][kt] 128x64, SW128
__device__ __half g_W1T[4][2][8192];        // W1 tiles [nt][kt] 128x64
__device__ __half g_xT[1024][8][8192];      // x fp16 tiles [rt][kt] 128x64, SW128
__device__ __half g_WihT[16][8][6144];      // W_ih [jc][kt] 96x64 gate-triple
__device__ __half g_WhhT[16][8][6144];      // W_hh [jc][kt] 96x64 gate-triple
__device__ __half g_hT[2][8][8][8192];      // h fp16 tiles ping-pong [mt][kt] 128x64
__device__ unsigned g_arrm[8][T_LEN];       // per-mt, per-step barrier counters

__device__ __forceinline__ float sigf(float x) {
    return __fdividef(1.0f, 1.0f + __expf(-x));
}
__device__ __forceinline__ float tanhfast(float x) {
    return 2.0f * sigf(2.0f * x) - 1.0f;
}

#define SW128(off) ((off) ^ (((off) >> 3) & 0x70))

__device__ __forceinline__ uint32_t smem_u32(const void* p) {
    uint32_t a;
    asm("{ .reg .u64 t; cvta.to.shared.u64 t, %1; cvt.u32.u64 %0, t; }" : "=r"(a) : "l"(p));
    return a;
}

#define MBAR_INIT(addr, cnt) \
    asm volatile("mbarrier.init.shared.b64 [%0], %1;" :: "r"(addr), "r"(cnt) : "memory")
#define MBAR_EXPECT(addr, bytes) \
    asm volatile("mbarrier.arrive.expect_tx.shared.b64 _, [%0], %1;" :: "r"(addr), "r"(bytes) : "memory")
#define FENCE_ASYNC() asm volatile("fence.proxy.async.shared::cta;" ::: "memory")

#define MBAR_WAIT_PARITY(addr, par) do {                                        \
    uint32_t _m = (addr); uint32_t _p = (par); uint32_t _d;                     \
    asm volatile("{\n\t.reg .pred p;\n\t"                                       \
        "mbarrier.try_wait.parity.acquire.cta.shared::cta.b64 p, [%1], %2;\n\t" \
        "selp.b32 %0, 1, 0, p;\n\t}" : "=r"(_d) : "r"(_m), "r"(_p) : "memory"); \
    if (!_d) {                                                                  \
        asm volatile("{\n\t.reg .pred P1;\n\t"                                  \
        "WL_%=:\n\t"                                                            \
        "mbarrier.try_wait.parity.acquire.cta.shared::cta.b64 P1, [%0], %1, 0x989680;\n\t" \
        "@P1 bra.uni WD_%=;\n\t"                                                \
        "bra.uni WL_%=;\n\t"                                                    \
        "WD_%=:\n\t}" :: "r"(_m), "r"(_p) : "memory");                          \
    }                                                                           \
} while (0)

#define BULK_G2S(dst, src, bytes, mbar) \
    asm volatile("cp.async.bulk.shared::cta.global.mbarrier::complete_tx::bytes [%0], [%1], %2, [%3];" \
        :: "r"(dst), "l"(src), "r"((uint32_t)(bytes)), "r"(mbar) : "memory")

__device__ __forceinline__ void ldsm4(uint32_t (&r)[4], uint32_t addr) {
    asm volatile("ldmatrix.sync.aligned.m8n8.x4.shared.b16 {%0,%1,%2,%3}, [%4];"
        : "=r"(r[0]), "=r"(r[1]), "=r"(r[2]), "=r"(r[3]) : "r"(addr));
}
__device__ __forceinline__ void mma16816(float (&c)[4], const uint32_t (&a)[4],
                                         uint32_t b0, uint32_t b1) {
    asm volatile(
        "mma.sync.aligned.m16n8k16.row.col.f32.f16.f16.f32 "
        "{%0,%1,%2,%3}, {%4,%5,%6,%7}, {%8,%9}, {%0,%1,%2,%3};"
        : "+f"(c[0]), "+f"(c[1]), "+f"(c[2]), "+f"(c[3])
        : "r"(a[0]), "r"(a[1]), "r"(a[2]), "r"(a[3]), "r"(b0), "r"(b1));
}

// ---------------- init ------------------------------------------------------
__global__ void init_kernel(float* __restrict__ out, const float* __restrict__ bv) {
    int i = blockIdx.x * blockDim.x + threadIdx.x;
    if (i < 262144) ((uint32_t*)&g_hT[0][0][0][0])[i] = 0u;   // zero h0 tiles
    if (i < ROWS) out[i] = bv[0];
    if (i < 8 * T_LEN) ((unsigned*)g_arrm)[i] = 0u;
}

// ---------------- obs -> fp16 swizzled tiles ---------------------------------
__global__ void obs_conv_kernel(const float* __restrict__ obs) {
    int i = blockIdx.x * blockDim.x + threadIdx.x;
    int d = (i & 63) * 2;
    int r = i >> 6;
    int t = r >> 10, n = r & 1023;
    size_t off = (size_t)(n >> 3) * 131072 + (size_t)t * 1024 + (size_t)(n & 7) * 128 + d;
    float2 v = *(const float2*)(obs + off);
    __half h0 = __float2half_rn(v.x);
    __half h1 = __float2half_rn(v.y);
    uint32_t ph = (uint32_t)__half_as_ushort(h0) | ((uint32_t)__half_as_ushort(h1) << 16);
    int rt = r >> 7, mloc = r & 127, kt = d >> 6, c = d & 63;
    *(uint32_t*)((char*)&g_oT[rt][kt][0] + SW128((uint32_t)(mloc * 128 + c * 2))) = ph;
}

// ---------------- prep: gate-triple reorder, single fp16 --------------------
__global__ void prep_kernel(const float* __restrict__ W_ih, const float* __restrict__ W_hh,
                            const float* __restrict__ W1) {
    int idx = blockIdx.x * blockDim.x + threadIdx.x;   // 786432
    if (idx >= G_DIM * H_DIM) return;
    int k = idx & 511, kt = k >> 6, c = k & 63;
    int jtr = idx >> 9;
    int jc = jtr / 96, rem = jtr % 96;
    int gt = rem >> 5, jl = rem & 31;
    size_t srow = (size_t)(gt * 512 + jc * 32 + jl);
    uint32_t off = SW128((uint32_t)(rem * 128 + c * 2));
    *(__half*)((char*)&g_WhhT[jc][kt][0] + off) = __float2half_rn(W_hh[srow * H_DIM + k]);
    *(__half*)((char*)&g_WihT[jc][kt][0] + off) = __float2half_rn(W_ih[srow * H_DIM + k]);
    // W1 [512][128] -> [nt 4][kt 2] 128x64 tiles
    if (idx < 65536) {
        int n = idx >> 7, d = idx & 127;
        int nt = n >> 7, m = n & 127;
        int ktd = d >> 6, cd = d & 63;
        uint32_t o2 = SW128((uint32_t)(m * 128 + cd * 2));
        *(__half*)((char*)&g_W1T[nt][ktd][0] + o2) = __float2half_rn(W1[idx]);
    }
}

// ---------------- gemm1: x = relu(obs @ W1^T + b1)  (fp16 HMMA) -------------
// grid (4 nt, 1024 rt). CTA 128m x 128n, K=128 (2 chunks). Stage 32KB x2.
__global__ __launch_bounds__(256, 2) void gemm1_kernel(const float* __restrict__ b1)
{
    extern __shared__ char smem[];
    const uint32_t sb = smem_u32(smem);
    const int tid = threadIdx.x;
    const int wid = tid >> 5, lane = tid & 31;
    const int mw = wid >> 1, nw = wid & 1;
    const int nt = blockIdx.x;
    const int rt = blockIdx.y;

    if (tid == 0) {
        MBAR_INIT(sb, 1);
        MBAR_INIT(sb + 8, 1);
        FENCE_ASYNC();
    }
    __syncthreads();

    float c[2][8][4] = {};

    if (tid == 0) {
#pragma unroll
        for (int ch = 0; ch < 2; ch++) {
            uint32_t mb = sb + ch * 8;
            uint32_t base = sb + 1024 + ch * 32768;
            MBAR_EXPECT(mb, 32768);
            BULK_G2S(base,         &g_oT[rt][ch][0],  16384, mb);
            BULK_G2S(base + 16384, &g_W1T[nt][ch][0], 16384, mb);
        }
    }

    for (int ch = 0; ch < 2; ch++) {
        MBAR_WAIT_PARITY(sb + ch * 8, 0);
        const uint32_t base = sb + 1024 + ch * 32768;
        const uint32_t sA = base, sB = base + 16384;
#pragma unroll
        for (int ks = 0; ks < 4; ks++) {
            uint32_t a[2][4];
            uint32_t arow0 = mw * 32 + (lane & 15);
            uint32_t acol = ks * 16 + ((lane >> 4) << 3);
#pragma unroll
            for (int mi = 0; mi < 2; mi++)
                ldsm4(a[mi], sA + SW128((arow0 + mi * 16) * 128 + acol * 2));
#pragma unroll
            for (int bp = 0; bp < 4; bp++) {
                uint32_t bh[4];
                uint32_t brow = nw * 64 + bp * 16 + (lane & 7) + ((lane >> 4) & 1) * 8;
                uint32_t bcol = ks * 16 + ((lane >> 3) & 1) * 8;
                ldsm4(bh, sB + SW128(brow * 128 + bcol * 2));
#pragma unroll
                for (int mi = 0; mi < 2; mi++) {
                    mma16816(c[mi][2 * bp],     a[mi], bh[0], bh[1]);
                    mma16816(c[mi][2 * bp + 1], a[mi], bh[2], bh[3]);
                }
            }
        }
    }

    const int n0 = nt * 128;
    const int g = lane >> 2, ct = lane & 3;
#pragma unroll
    for (int mi = 0; mi < 2; mi++) {
#pragma unroll
        for (int ntl = 0; ntl < 8; ntl++) {
            int mloc = mw * 32 + mi * 16 + g;
            int col = n0 + nw * 64 + ntl * 8 + ct * 2;
            float2 bi = *(const float2*)(b1 + col);
            float v0x = fmaxf(c[mi][ntl][0] + bi.x, 0.0f);
            float v0y = fmaxf(c[mi][ntl][1] + bi.y, 0.0f);
            float v1x = fmaxf(c[mi][ntl][2] + bi.x, 0.0f);
            float v1y = fmaxf(c[mi][ntl][3] + bi.y, 0.0f);
            int kt = col >> 6, cc = col & 63;
            uint32_t p0 = (uint32_t)__half_as_ushort(__float2half_rn(v0x))
                        | ((uint32_t)__half_as_ushort(__float2half_rn(v0y)) << 16);
            uint32_t p1 = (uint32_t)__half_as_ushort(__float2half_rn(v1x))
                        | ((uint32_t)__half_as_ushort(__float2half_rn(v1y)) << 16);
            *(uint32_t*)((char*)&g_xT[rt][kt][0] + SW128((uint32_t)(mloc * 128 + cc * 2)))       = p0;
            *(uint32_t*)((char*)&g_xT[rt][kt][0] + SW128((uint32_t)((mloc + 8) * 128 + cc * 2))) = p1;
        }
    }
}

// ---------------- fused persistent GRU scan (single-pass fp16) --------------
// grid (16 jc, 8 mt). Per step: gh = h@W_hh^T and gi = x_t@W_ih^T
// (128m x 96 gate-triple, K=512). 4-stage pipeline, stage = 56KB:
// h@0 (16K), x@16K (16K), Whh@32K (12K), Wih@45056 (12K).
// total smem = 1024 + 4*57344 = 230400.
#define STG 57344
#define OFF_X  16384
#define OFF_WH 32768
#define OFF_WI 45056

__global__ __launch_bounds__(256, 1) void gru_persist_kernel(
    const float* __restrict__ b_hh, const float* __restrict__ b_ih,
    const float* __restrict__ Wv, float* __restrict__ out)
{
    extern __shared__ char smem[];
    const uint32_t sb = smem_u32(smem);
    const int tid = threadIdx.x;
    const int wid = tid >> 5, lane = tid & 31;
    const int jc = blockIdx.x;    // 0..15
    const int mt = blockIdx.y;    // 0..7

    // mbars: pH[4] @ sb+0..24, pX[4] @ sb+32..56
    if (tid == 0) {
#pragma unroll
        for (int b = 0; b < 4; b++) {
            MBAR_INIT(sb + b * 8, 1);
            MBAR_INIT(sb + 32 + b * 8, 1);
        }
        FENCE_ASYNC();
    }
    __syncthreads();

    const uint32_t S0 = sb + 1024;

    // per-thread constants
    const int g = lane >> 2, ct = lane & 3;
    const int jbase = jc * 32;
    float2 brv[4], bzv[4], bniv[4], bnhv[4], wvv[4];
#pragma unroll
    for (int jj = 0; jj < 4; jj++) {
        int j = jbase + jj * 8 + ct * 2;
        float2 ir = *(const float2*)(b_ih + j);
        float2 hr = *(const float2*)(b_hh + j);
        brv[jj].x = ir.x + hr.x; brv[jj].y = ir.y + hr.y;
        float2 iz = *(const float2*)(b_ih + 512 + j);
        float2 hz = *(const float2*)(b_hh + 512 + j);
        bzv[jj].x = iz.x + hz.x; bzv[jj].y = iz.y + hz.y;
        bniv[jj] = *(const float2*)(b_ih + 1024 + j);
        bnhv[jj] = *(const float2*)(b_hh + 1024 + j);
        wvv[jj]  = *(const float2*)(Wv + j);
    }
    float hreg[2][4][2];
#pragma unroll
    for (int mi = 0; mi < 2; mi++)
#pragma unroll
        for (int jj = 0; jj < 4; jj++)
            hreg[mi][jj][0] = hreg[mi][jj][1] = 0.0f;

    int pH[4] = {0, 0, 0, 0}, pX[4] = {0, 0, 0, 0};

    auto issueH = [&](int t, int ch) {
        int buf = ch & 3;
        uint32_t mb = sb + buf * 8;
        MBAR_EXPECT(mb, 16384);
        BULK_G2S(S0 + buf * STG, &g_hT[t & 1][mt][ch][0], 16384, mb);
    };
    auto issueXW = [&](int t, int ch) {
        int buf = ch & 3;
        uint32_t mb = sb + 32 + buf * 8;
        uint32_t base = S0 + buf * STG;
        MBAR_EXPECT(mb, 40960);
        BULK_G2S(base + OFF_X,  &g_xT[t * 8 + mt][ch][0], 16384, mb);
        BULK_G2S(base + OFF_WH, &g_WhhT[jc][ch][0],       12288, mb);
        BULK_G2S(base + OFF_WI, &g_WihT[jc][ch][0],       12288, mb);
    };

    if (tid == 0) {
#pragma unroll
        for (int c2 = 0; c2 < 4; c2++) { issueXW(0, c2); issueH(0, c2); }
    }

    for (int t = 0; t < T_LEN; t++) {
        float cg[12][4] = {};   // gh accumulators
        float ci[12][4] = {};   // gi accumulators

        for (int ch = 0; ch < 8; ch++) {
            const int buf = ch & 3;
            MBAR_WAIT_PARITY(sb + buf * 8, pH[buf]);       pH[buf] ^= 1;
            MBAR_WAIT_PARITY(sb + 32 + buf * 8, pX[buf]);  pX[buf] ^= 1;
            const uint32_t base = S0 + buf * STG;

#pragma unroll
            for (int ks = 0; ks < 4; ks++) {
                uint32_t ah[4], ax[4];
                uint32_t arow = wid * 16 + (lane & 15);
                uint32_t acol = ks * 16 + ((lane >> 4) << 3);
                uint32_t aoff = SW128(arow * 128 + acol * 2);
                ldsm4(ah, base + aoff);
                ldsm4(ax, base + OFF_X + aoff);
#pragma unroll
                for (int bt = 0; bt < 6; bt++) {
                    uint32_t wh[4], wi[4];
                    uint32_t brow = bt * 16 + (lane & 7) + ((lane >> 4) & 1) * 8;
                    uint32_t bcol = ks * 16 + ((lane >> 3) & 1) * 8;
                    uint32_t boff = SW128(brow * 128 + bcol * 2);
                    ldsm4(wh, base + OFF_WH + boff);
                    ldsm4(wi, base + OFF_WI + boff);
                    mma16816(cg[2 * bt],     ah, wh[0], wh[1]);
                    mma16816(cg[2 * bt + 1], ah, wh[2], wh[3]);
                    mma16816(ci[2 * bt],     ax, wi[0], wi[1]);
                    mma16816(ci[2 * bt + 1], ax, wi[2], wi[3]);
                }
            }
            __syncthreads();
            if (tid == 0) {
                if (ch < 4) {
                    issueH(t, ch + 4);
                    issueXW(t, ch + 4);
                } else if (t + 1 < T_LEN) {
                    issueXW(t + 1, ch - 4);     // next-step x/W into freed buffer
                }
            }
        }

        // ---------------- fused epilogue ----------------
        const int wr = (t + 1) & 1;
#pragma unroll
        for (int mi = 0; mi < 2; mi++) {
            int mloc = wid * 16 + g + mi * 8;
            int m_g = mt * 128 + mloc;

            float vp = 0.0f;
#pragma unroll
            for (int jj = 0; jj < 4; jj++) {
                int jl = jj * 8 + ct * 2;
                int j  = jbase + jl;

                float r0 = sigf(ci[jj][mi * 2]     + cg[jj][mi * 2]     + brv[jj].x);
                float r1 = sigf(ci[jj][mi * 2 + 1] + cg[jj][mi * 2 + 1] + brv[jj].y);
                float z0 = sigf(ci[4 + jj][mi * 2]     + cg[4 + jj][mi * 2]     + bzv[jj].x);
                float z1 = sigf(ci[4 + jj][mi * 2 + 1] + cg[4 + jj][mi * 2 + 1] + bzv[jj].y);
                float nt0 = tanhfast(ci[8 + jj][mi * 2]     + bniv[jj].x
                                     + r0 * (cg[8 + jj][mi * 2]     + bnhv[jj].x));
                float nt1 = tanhfast(ci[8 + jj][mi * 2 + 1] + bniv[jj].y
                                     + r1 * (cg[8 + jj][mi * 2 + 1] + bnhv[jj].y));
                float h0 = (1.0f - z0) * nt0 + z0 * hreg[mi][jj][0];
                float h1 = (1.0f - z1) * nt1 + z1 * hreg[mi][jj][1];
                hreg[mi][jj][0] = h0;
                hreg[mi][jj][1] = h1;

                __half hh0 = __float2half_rn(h0);
                __half hh1 = __float2half_rn(h1);
                uint32_t ph = (uint32_t)__half_as_ushort(hh0) | ((uint32_t)__half_as_ushort(hh1) << 16);
                int kt = j >> 6, cc = j & 63;
                uint32_t off = SW128((uint32_t)(mloc * 128 + cc * 2));
                *(uint32_t*)((char*)&g_hT[wr][mt][kt][0] + off) = ph;

                vp = fmaf(wvv[jj].x, h0, vp);
                vp = fmaf(wvv[jj].y, h1, vp);
            }
            vp += __shfl_xor_sync(0xffffffffu, vp, 1);
            vp += __shfl_xor_sync(0xffffffffu, vp, 2);
            if (ct == 0) {
                int bs = m_g >> 3, a = m_g & 7;
                atomicAdd(&out[((size_t)bs * T_LEN + t) * 8 + a], vp);
            }
        }

        // ---------------- per-mt grid barrier (16 arrivals) ----------------
        if (t < T_LEN - 1) {
            __threadfence();
            __syncthreads();
            if (tid == 0) {
                atomicAdd(&g_arrm[mt][t], 1u);
                while (((volatile unsigned*)g_arrm[mt])[t] < 16u) { }
                __threadfence();
#pragma unroll
                for (int c2 = 0; c2 < 4; c2++) issueH(t + 1, c2);
            }
            __syncthreads();
        }
    }
}

// ---------------------------------------------------------------------------
extern "C" void kernel_launch(void* const* d_in, const int* in_sizes, int n_in,
                              void* d_out, int out_size)
{
    const float* obs  = (const float*)d_in[0];
    const float* W1   = (const float*)d_in[1];
    const float* b1   = (const float*)d_in[2];
    const float* W_ih = (const float*)d_in[3];
    const float* b_ih = (const float*)d_in[4];
    const float* W_hh = (const float*)d_in[5];
    const float* b_hh = (const float*)d_in[6];
    const float* Wv   = (const float*)d_in[7];
    const float* bv   = (const float*)d_in[8];
    float* out = (float*)d_out;

    cudaFuncSetAttribute(gemm1_kernel,       cudaFuncAttributeMaxDynamicSharedMemorySize, 66560);
    cudaFuncSetAttribute(gru_persist_kernel, cudaFuncAttributeMaxDynamicSharedMemorySize, 230400);

    init_kernel<<<2048, 256>>>(out, bv);
    obs_conv_kernel<<<32768, 256>>>(obs);
    prep_kernel<<<3072, 256>>>(W_ih, W_hh, W1);
    gemm1_kernel<<<dim3(4, 1024), 256, 66560>>>(b1);
    gru_persist_kernel<<<dim3(16, 8), 256, 230400>>>(b_hh, b_ih, Wv, out);
}